// round 13
// baseline (speedup 1.0000x reference)
#include <cuda_runtime.h>
#include <cuda_bf16.h>
#include <cuda_fp16.h>
#include <cstdint>

#define Bb 4
#define Ss 1024
#define Dd 1024
#define Hh 16
#define DHh 64
#define SCALE 0.125f

// ---------------- scratch (device globals; no allocation allowed) ----------------
__device__ uint32_t g_Qt[Bb * Hh * Ss * DHh]; // tf32 bits [b][h][s][d]
__device__ uint32_t g_Kt[Bb * Hh * Ss * DHh];
__device__ __half   g_Vh[Bb * Hh * Ss * DHh]; // V as fp16
__device__ float g_CQ[Bb * Ss * DHh];
__device__ float g_CK[Bb * Ss * DHh];
__device__ float g_qsig[Bb * Ss * Ss];        // sigmoid quasi scores (head-invariant)

__device__ __forceinline__ float sigmoidf_(float x) { return 1.0f / (1.0f + __expf(-x)); }

__device__ __forceinline__ uint32_t f2tf(float x) {
    uint32_t r; asm("cvt.rna.tf32.f32 %0, %1;" : "=r"(r) : "f"(x)); return r;
}

__device__ __forceinline__ void mma_tf32(float* d, const uint32_t* a, const uint32_t* b) {
    asm volatile(
        "mma.sync.aligned.m16n8k8.row.col.f32.tf32.tf32.f32 "
        "{%0,%1,%2,%3}, {%4,%5,%6,%7}, {%8,%9}, {%0,%1,%2,%3};"
        : "+f"(d[0]), "+f"(d[1]), "+f"(d[2]), "+f"(d[3])
        : "r"(a[0]), "r"(a[1]), "r"(a[2]), "r"(a[3]), "r"(b[0]), "r"(b[1]));
}

__device__ __forceinline__ void mma_f16(float* d, const uint32_t* a, const uint32_t* b) {
    asm volatile(
        "mma.sync.aligned.m16n8k16.row.col.f32.f16.f16.f32 "
        "{%0,%1,%2,%3}, {%4,%5,%6,%7}, {%8,%9}, {%0,%1,%2,%3};"
        : "+f"(d[0]), "+f"(d[1]), "+f"(d[2]), "+f"(d[3])
        : "r"(a[0]), "r"(a[1]), "r"(a[2]), "r"(a[3]), "r"(b[0]), "r"(b[1]));
}

// ---------------- kernel 0: tf32 MMA CQ|CK GEMM -----------------------------------
__global__ __launch_bounds__(256, 2) void cqck_mma(
    const float* __restrict__ A,
    const float* __restrict__ Wcq, const float* __restrict__ bcq,
    const float* __restrict__ Wck, const float* __restrict__ bck)
{
    __shared__ uint32_t As[128][36];
    __shared__ uint32_t Bs[32][132];

    const int bm = blockIdx.x;
    const int tid = threadIdx.x;
    const int warpId = tid >> 5, lane = tid & 31;
    const int warpM = warpId & 1, warpN = warpId >> 1;
    const int gr = lane >> 2, gc = lane & 3;

    float acc[4][4][4];
#pragma unroll
    for (int i = 0; i < 4; i++)
#pragma unroll
        for (int j = 0; j < 4; j++)
#pragma unroll
            for (int t = 0; t < 4; t++) acc[i][j][t] = 0.0f;

    for (int k0 = 0; k0 < 1024; k0 += 32) {
#pragma unroll
        for (int i = 0; i < 4; i++) {
            int idx = tid + i * 256;
            int r = idx >> 3, c4 = idx & 7;
            float4 v = *(const float4*)&A[(size_t)(bm * 128 + r) * 1024 + k0 + c4 * 4];
            uint4 t = {f2tf(v.x), f2tf(v.y), f2tf(v.z), f2tf(v.w)};
            *(uint4*)&As[r][c4 * 4] = t;
        }
#pragma unroll
        for (int i = 0; i < 4; i++) {
            int idx = tid + i * 256;
            int row = idx >> 5;
            int c4  = idx & 31;
            int col = c4 * 4;
            const float* src = (col < 64)
                ? &Wcq[(size_t)(k0 + row) * 64 + col]
                : &Wck[(size_t)(k0 + row) * 64 + (col - 64)];
            float4 v = *(const float4*)src;
            uint4 t = {f2tf(v.x), f2tf(v.y), f2tf(v.z), f2tf(v.w)};
            *(uint4*)&Bs[row][col] = t;
        }
        __syncthreads();

#pragma unroll
        for (int ks = 0; ks < 4; ks++) {
            const int kb = ks * 8;
            uint32_t af[4][4];
#pragma unroll
            for (int mt = 0; mt < 4; mt++) {
                int m = warpM * 64 + mt * 16;
                af[mt][0] = As[m + gr][kb + gc];
                af[mt][1] = As[m + gr + 8][kb + gc];
                af[mt][2] = As[m + gr][kb + gc + 4];
                af[mt][3] = As[m + gr + 8][kb + gc + 4];
            }
            uint32_t bf[4][2];
#pragma unroll
            for (int nt = 0; nt < 4; nt++) {
                int n = warpN * 32 + nt * 8 + gr;
                bf[nt][0] = Bs[kb + gc][n];
                bf[nt][1] = Bs[kb + gc + 4][n];
            }
#pragma unroll
            for (int mt = 0; mt < 4; mt++)
#pragma unroll
                for (int nt = 0; nt < 4; nt++)
                    mma_tf32(acc[mt][nt], af[mt], bf[nt]);
        }
        __syncthreads();
    }

#pragma unroll
    for (int mt = 0; mt < 4; mt++) {
        int m0 = bm * 128 + warpM * 64 + mt * 16 + gr;
#pragma unroll
        for (int half = 0; half < 2; half++) {
            int m = m0 + half * 8;
#pragma unroll
            for (int nt = 0; nt < 4; nt++) {
                int n = warpN * 32 + nt * 8 + gc * 2;
                float2 v;
                if (n < 64) {
                    v.x = acc[mt][nt][half * 2 + 0] + bcq[n];
                    v.y = acc[mt][nt][half * 2 + 1] + bcq[n + 1];
                    *(float2*)&g_CQ[(size_t)m * 64 + n] = v;
                } else {
                    v.x = acc[mt][nt][half * 2 + 0] + bck[n - 64];
                    v.y = acc[mt][nt][half * 2 + 1] + bck[n - 63];
                    *(float2*)&g_CK[(size_t)m * 64 + (n - 64)] = v;
                }
            }
        }
    }
}

// ---------------- kernel 1: head-invariant quasi sigmoid [B,S,S] ------------------
__global__ __launch_bounds__(256) void qsig_kernel(const float* __restrict__ mask)
{
    __shared__ float Qs[64 * 68];
    __shared__ float Ks[64 * 68];
    const int bi = blockIdx.z, qt = blockIdx.y, kt = blockIdx.x;
    const int tid = threadIdx.x;
    const int tx = tid & 15, ty = tid >> 4;

#pragma unroll
    for (int i = 0; i < 4; i++) {
        int idx = tid + i * 256;
        int m = idx >> 4, c4 = idx & 15;
        float4 vq = *(const float4*)&g_CQ[((size_t)(bi * Ss + qt * 64 + m)) * 64 + c4 * 4];
        float4 vk = *(const float4*)&g_CK[((size_t)(bi * Ss + kt * 64 + m)) * 64 + c4 * 4];
        Qs[(c4 * 4 + 0) * 68 + m] = vq.x; Qs[(c4 * 4 + 1) * 68 + m] = vq.y;
        Qs[(c4 * 4 + 2) * 68 + m] = vq.z; Qs[(c4 * 4 + 3) * 68 + m] = vq.w;
        Ks[(c4 * 4 + 0) * 68 + m] = vk.x; Ks[(c4 * 4 + 1) * 68 + m] = vk.y;
        Ks[(c4 * 4 + 2) * 68 + m] = vk.z; Ks[(c4 * 4 + 3) * 68 + m] = vk.w;
    }
    __syncthreads();

    float acc[4][4];
#pragma unroll
    for (int i = 0; i < 4; i++)
#pragma unroll
        for (int j = 0; j < 4; j++) acc[i][j] = 0.0f;

#pragma unroll 4
    for (int d = 0; d < 64; d++) {
        float4 a4 = *(float4*)&Qs[d * 68 + ty * 4];
        float4 b4 = *(float4*)&Ks[d * 68 + tx * 4];
        float a[4] = {a4.x, a4.y, a4.z, a4.w};
        float bv[4] = {b4.x, b4.y, b4.z, b4.w};
#pragma unroll
        for (int i = 0; i < 4; i++)
#pragma unroll
            for (int j = 0; j < 4; j++) acc[i][j] += a[i] * bv[j];
    }
#pragma unroll
    for (int i = 0; i < 4; i++) {
        int qrow = qt * 64 + ty * 4 + i;
#pragma unroll
        for (int j = 0; j < 4; j++) {
            int kcol = kt * 64 + tx * 4 + j;
            float v = sigmoidf_(acc[i][j] * SCALE + mask[bi * Ss + kcol]);
            g_qsig[((size_t)(bi * Ss + qrow)) * Ss + kcol] = v;
        }
    }
}

// ---------------- kernel 2: tf32 projection GEMM, inline cvt, grid z=3 -----------
__global__ __launch_bounds__(256, 2) void proj_mma(
    const float* __restrict__ hidden,
    const float* __restrict__ Wq, const float* __restrict__ Wk, const float* __restrict__ Wv,
    const float* __restrict__ bq, const float* __restrict__ bk, const float* __restrict__ bv)
{
    __shared__ uint32_t As[128][36];
    __shared__ uint32_t Bs[32][132];

    const int which = blockIdx.z;
    const float* W = (which == 0) ? Wq : (which == 1) ? Wk : Wv;
    const float* bias = (which == 0) ? bq : (which == 1) ? bk : bv;
    uint32_t* outt = (which == 0) ? g_Qt : g_Kt;

    const int bm = blockIdx.y, bn = blockIdx.x;
    const int tid = threadIdx.x;
    const int warpId = tid >> 5, lane = tid & 31;
    const int warpM = warpId & 1, warpN = warpId >> 1;
    const int gr = lane >> 2, gc = lane & 3;

    float acc[4][4][4];
#pragma unroll
    for (int i = 0; i < 4; i++)
#pragma unroll
        for (int j = 0; j < 4; j++)
#pragma unroll
            for (int t = 0; t < 4; t++) acc[i][j][t] = 0.0f;

    for (int k0 = 0; k0 < 1024; k0 += 32) {
#pragma unroll
        for (int i = 0; i < 4; i++) {
            int idx = tid + i * 256;
            int r = idx >> 3, c4 = idx & 7;
            float4 v = *(const float4*)&hidden[(size_t)(bm * 128 + r) * 1024 + k0 + c4 * 4];
            uint4 t = {f2tf(v.x), f2tf(v.y), f2tf(v.z), f2tf(v.w)};
            *(uint4*)&As[r][c4 * 4] = t;
        }
#pragma unroll
        for (int i = 0; i < 4; i++) {
            int idx = tid + i * 256;
            int row = idx >> 5, c4 = idx & 31;
            float4 v = *(const float4*)&W[(size_t)(k0 + row) * 1024 + bn * 128 + c4 * 4];
            uint4 t = {f2tf(v.x), f2tf(v.y), f2tf(v.z), f2tf(v.w)};
            *(uint4*)&Bs[row][c4 * 4] = t;
        }
        __syncthreads();

#pragma unroll
        for (int ks = 0; ks < 4; ks++) {
            const int kb = ks * 8;
            uint32_t af[4][4];
#pragma unroll
            for (int mt = 0; mt < 4; mt++) {
                int m = warpM * 64 + mt * 16;
                af[mt][0] = As[m + gr][kb + gc];
                af[mt][1] = As[m + gr + 8][kb + gc];
                af[mt][2] = As[m + gr][kb + gc + 4];
                af[mt][3] = As[m + gr + 8][kb + gc + 4];
            }
            uint32_t bf[4][2];
#pragma unroll
            for (int nt = 0; nt < 4; nt++) {
                int n = warpN * 32 + nt * 8 + gr;
                bf[nt][0] = Bs[kb + gc][n];
                bf[nt][1] = Bs[kb + gc + 4][n];
            }
#pragma unroll
            for (int mt = 0; mt < 4; mt++)
#pragma unroll
                for (int nt = 0; nt < 4; nt++)
                    mma_tf32(acc[mt][nt], af[mt], bf[nt]);
        }
        __syncthreads();
    }

#pragma unroll
    for (int mt = 0; mt < 4; mt++) {
        int m0 = bm * 128 + warpM * 64 + mt * 16 + gr;
#pragma unroll
        for (int half = 0; half < 2; half++) {
            int m = m0 + half * 8;
            int b = m >> 10, s = m & 1023;
#pragma unroll
            for (int nt = 0; nt < 4; nt++) {
                int n = bn * 128 + warpN * 32 + nt * 8 + gc * 2;
                int h = n >> 6, d = n & 63;
                size_t o = (((size_t)(b * Hh + h) * Ss + s)) * 64 + d;
                float vx = acc[mt][nt][half * 2 + 0] + bias[n];
                float vy = acc[mt][nt][half * 2 + 1] + bias[n + 1];
                if (which == 2) {
                    *(__half2*)&g_Vh[o] = __floats2half2_rn(vx, vy);
                } else {
                    uint2 tv = {f2tf(vx), f2tf(vy)};
                    *(uint2*)&outt[o] = tv;
                }
            }
        }
    }
}

// ---------------- kernel 3: fused attention A+B+C ---------------------------------
// 256 threads, 8 warps (2m x 4n); 32 q-rows.
// smem: Ks[128*68]*4 (reused as Vt[64][136] half) + Qtf[32*68]*4 + Sc[32*1048]*2
//       + red/inv/lam  = 111360 B -> 2 blocks/SM.
#define SC_H 1048
#define ATTN_SMEM (128 * 68 * 4 + 32 * 68 * 4 + 32 * SC_H * 2 + (32 * 4 + 32 + 32) * 4)

__global__ __launch_bounds__(256, 2) void attn_fused(
    const float* __restrict__ mask, float* __restrict__ out,
    const float* __restrict__ wlqc, const float* __restrict__ wlqq,
    const float* __restrict__ wlkc, const float* __restrict__ wlkk)
{
    extern __shared__ uint32_t smu[];
    uint32_t* Ks  = smu;                         // 128*68 u32 (phase A) / Vt (phase C)
    uint32_t* Qtf = Ks + 128 * 68;               // 32*68 u32
    __half* Sc    = (__half*)(Qtf + 32 * 68);    // 32*1048 half
    float* red    = (float*)(Sc + 32 * SC_H);    // [32][4]
    float* inv_s  = red + 32 * 4;                // 32
    float* lam_s  = inv_s + 32;                  // 32

    const int qb = blockIdx.x;
    const int bh = blockIdx.y;
    const int bi = bh >> 4, hi = bh & 15;
    const int tid = threadIdx.x;
    const int w = tid >> 5, lane = tid & 31;
    const int gr = lane >> 2, gc = lane & 3;
    const int wm = w >> 2, wn = w & 3;           // 2m x 4n warp grid

    const uint32_t* Qtg = &g_Qt[((size_t)bh * Ss + qb * 32) * 64];
    const uint32_t* Ktg = &g_Kt[(size_t)bh * Ss * 64];
    const float* maskb = &mask[bi * Ss];

    const size_t OFF_NEW   = (size_t)Bb * Ss * Dd;
    const size_t OFF_PROBS = OFF_NEW + (size_t)Bb * Hh * Ss * Ss;
    const size_t OFF_QUASI = OFF_PROBS + (size_t)Bb * Hh * Ss * Ss;

    // load Q tile [32][64] tf32 bits
#pragma unroll
    for (int i = 0; i < 2; i++) {
        int idx = tid + i * 256;
        int m = idx >> 4, c4 = idx & 15;
        uint4 v = *(const uint4*)&Qtg[(size_t)m * 64 + c4 * 4];
        *(uint4*)&Qtf[m * 68 + c4 * 4] = v;
    }

    // lambda_context (tf32 bits reinterpret as fp32; 8 threads per row)
    {
        int r = tid >> 3;          // 0..31
        int j = tid & 7;           // 0..7
        int qrow = qb * 32 + r;
        const float* cq = &g_CQ[((size_t)(bi * Ss + qrow)) * 64];
        const float* ck = &g_CK[((size_t)(bi * Ss + qrow)) * 64];
        const uint32_t* qp = &g_Qt[((size_t)bh * Ss + qrow) * 64];
        const uint32_t* kp = &g_Kt[((size_t)bh * Ss + qrow) * 64];
        float sq = 0.f, sk = 0.f;
#pragma unroll
        for (int d0 = 0; d0 < 8; d0++) {
            int d = j * 8 + d0;
            sq += cq[d] * wlqc[d] + __uint_as_float(qp[d]) * wlqq[d];
            sk += ck[d] * wlkc[d] + __uint_as_float(kp[d]) * wlkk[d];
        }
#pragma unroll
        for (int o = 4; o > 0; o >>= 1) {
            sq += __shfl_xor_sync(0xffffffffu, sq, o);
            sk += __shfl_xor_sync(0xffffffffu, sk, o);
        }
        if (j == 0) lam_s[r] = 1.0f - sigmoidf_(sq) - sigmoidf_(sk);
    }

    const int row0 = wm * 16 + gr;          // this thread's rows: row0, row0+8
    float rsum0 = 0.0f, rsum1 = 0.0f;

    // ---------- Phase A: scores -> exp -> half Sc, accumulate row sums ----------
    for (int nt = 0; nt < 8; nt++) {
#pragma unroll
        for (int i = 0; i < 8; i++) {
            int idx = tid + i * 256;          // 0..2047
            int n = idx >> 4, c4 = idx & 15;
            uint4 v = *(const uint4*)&Ktg[((size_t)(nt * 128 + n)) * 64 + c4 * 4];
            *(uint4*)&Ks[n * 68 + c4 * 4] = v;
        }
        __syncthreads();

        float acc[4][4];
#pragma unroll
        for (int t = 0; t < 4; t++)
#pragma unroll
            for (int e = 0; e < 4; e++) acc[t][e] = 0.0f;

#pragma unroll
        for (int ks = 0; ks < 8; ks++) {
            const int kb = ks * 8;
            uint32_t af[4];
            af[0] = Qtf[(wm * 16 + gr) * 68 + kb + gc];
            af[1] = Qtf[(wm * 16 + gr + 8) * 68 + kb + gc];
            af[2] = Qtf[(wm * 16 + gr) * 68 + kb + gc + 4];
            af[3] = Qtf[(wm * 16 + gr + 8) * 68 + kb + gc + 4];
#pragma unroll
            for (int t = 0; t < 4; t++) {
                int n0 = wn * 32 + t * 8;
                uint32_t bf[2];
                bf[0] = Ks[(n0 + gr) * 68 + kb + gc];
                bf[1] = Ks[(n0 + gr) * 68 + kb + gc + 4];
                mma_tf32(acc[t], af, bf);
            }
        }

#pragma unroll
        for (int t = 0; t < 4; t++) {
            int col = nt * 128 + wn * 32 + t * 8 + gc * 2;
            float mk0 = maskb[col], mk1 = maskb[col + 1];
            float e00 = __expf(acc[t][0] * SCALE + mk0);
            float e01 = __expf(acc[t][1] * SCALE + mk1);
            float e10 = __expf(acc[t][2] * SCALE + mk0);
            float e11 = __expf(acc[t][3] * SCALE + mk1);
            rsum0 += e00 + e01;
            rsum1 += e10 + e11;
            *(__half2*)&Sc[row0 * SC_H + col] = __floats2half2_rn(e00, e01);
            *(__half2*)&Sc[(row0 + 8) * SC_H + col] = __floats2half2_rn(e10, e11);
        }
        __syncthreads();
    }

    // reduce sums: over gc lanes, then across the 4 n-warps
    rsum0 += __shfl_xor_sync(0xffffffffu, rsum0, 1);
    rsum0 += __shfl_xor_sync(0xffffffffu, rsum0, 2);
    rsum1 += __shfl_xor_sync(0xffffffffu, rsum1, 1);
    rsum1 += __shfl_xor_sync(0xffffffffu, rsum1, 2);
    if (gc == 0) {
        red[row0 * 4 + wn] = rsum0;
        red[(row0 + 8) * 4 + wn] = rsum1;
    }
    __syncthreads();
    if (tid < 32) {
        float s = red[tid * 4] + red[tid * 4 + 1] + red[tid * 4 + 2] + red[tid * 4 + 3];
        inv_s[tid] = 1.0f / s;
    }
    __syncthreads();

    // ---------- Phase B: stream probs/quasi/new; write newP(fp16) back to Sc ------
    for (int r = w * 4; r < w * 4 + 4; r++) {
        const float inv = inv_s[r];
        const float lam = lam_s[r];
        const int qrow = qb * 32 + r;
        const float* qs_row = &g_qsig[((size_t)(bi * Ss + qrow)) * Ss];
        const size_t rowbase = ((size_t)bh * Ss + qrow) * Ss;
        float* probs_row = out + OFF_PROBS + rowbase;
        float* quasi_row = out + OFF_QUASI + rowbase;
        float* new_row   = out + OFF_NEW + rowbase;

        for (int c8 = lane; c8 < 128; c8 += 32) {
            int col = c8 * 8;
            uint4 hv = *(uint4*)&Sc[r * SC_H + col];
            const __half2* hp = (const __half2*)&hv;
            float2 e01 = __half22float2(hp[0]);
            float2 e23 = __half22float2(hp[1]);
            float2 e45 = __half22float2(hp[2]);
            float2 e67 = __half22float2(hp[3]);
            float4 p0 = {e01.x * inv, e01.y * inv, e23.x * inv, e23.y * inv};
            float4 p1 = {e45.x * inv, e45.y * inv, e67.x * inv, e67.y * inv};
            float4 qs0 = *(const float4*)&qs_row[col];
            float4 qs1 = *(const float4*)&qs_row[col + 4];
            float4 qp0 = {lam * qs0.x, lam * qs0.y, lam * qs0.z, lam * qs0.w};
            float4 qp1 = {lam * qs1.x, lam * qs1.y, lam * qs1.z, lam * qs1.w};
            float4 n0 = {p0.x + qp0.x, p0.y + qp0.y, p0.z + qp0.z, p0.w + qp0.w};
            float4 n1 = {p1.x + qp1.x, p1.y + qp1.y, p1.z + qp1.z, p1.w + qp1.w};
            *(float4*)&probs_row[col] = p0;     *(float4*)&probs_row[col + 4] = p1;
            *(float4*)&quasi_row[col] = qp0;    *(float4*)&quasi_row[col + 4] = qp1;
            *(float4*)&new_row[col] = n0;       *(float4*)&new_row[col + 4] = n1;
            // write newP back to Sc as fp16 for phase C
            uint4 nh;
            ((__half2*)&nh)[0] = __floats2half2_rn(n0.x, n0.y);
            ((__half2*)&nh)[1] = __floats2half2_rn(n0.z, n0.w);
            ((__half2*)&nh)[2] = __floats2half2_rn(n1.x, n1.y);
            ((__half2*)&nh)[3] = __floats2half2_rn(n1.z, n1.w);
            *(uint4*)&Sc[r * SC_H + col] = nh;
        }
    }
    __syncthreads();

    // ---------- Phase C: ctx[32][64] = newP(fp16) @ V(fp16), m16n8k16 -------------
    {
        __half* Vt = (__half*)Ks;        // [64][136] halfs (transposed V chunk)
        const __half* Vhg = &g_Vh[(size_t)bh * Ss * 64];

        float accC[2][4];
#pragma unroll
        for (int t = 0; t < 2; t++)
#pragma unroll
            for (int e = 0; e < 4; e++) accC[t][e] = 0.0f;

        for (int vt = 0; vt < 8; vt++) {
            // load V chunk rows vt*128..+127 coalesced, transpose into Vt[d][s]
#pragma unroll
            for (int i = 0; i < 4; i++) {
                int idx = tid + i * 256;          // 0..1023
                int s = idx >> 3, d8 = idx & 7;
                uint4 v = *(const uint4*)&Vhg[((size_t)(vt * 128 + s)) * 64 + d8 * 8];
                const __half* hv = (const __half*)&v;
#pragma unroll
                for (int j = 0; j < 8; j++)
                    Vt[(d8 * 8 + j) * 136 + s] = hv[j];
            }
            __syncthreads();

#pragma unroll
            for (int ks = 0; ks < 8; ks++) {
                int k0 = ks * 16;                 // within-chunk k base
                int kg = vt * 128 + k0;           // Sc column base
                uint32_t a[4];
                a[0] = *(const uint32_t*)&Sc[(wm * 16 + gr) * SC_H + kg + 2 * gc];
                a[1] = *(const uint32_t*)&Sc[(wm * 16 + gr + 8) * SC_H + kg + 2 * gc];
                a[2] = *(const uint32_t*)&Sc[(wm * 16 + gr) * SC_H + kg + 2 * gc + 8];
                a[3] = *(const uint32_t*)&Sc[(wm * 16 + gr + 8) * SC_H + kg + 2 * gc + 8];
#pragma unroll
                for (int t = 0; t < 2; t++) {
                    int n0 = wn * 16 + t * 8;
                    uint32_t b[2];
                    b[0] = *(const uint32_t*)&Vt[(n0 + gr) * 136 + k0 + 2 * gc];
                    b[1] = *(const uint32_t*)&Vt[(n0 + gr) * 136 + k0 + 2 * gc + 8];
                    mma_f16(accC[t], a, b);
                }
            }
            __syncthreads();
        }

        // epilogue: ctx writes
        int rowg = qb * 32 + wm * 16 + gr;
#pragma unroll
        for (int t = 0; t < 2; t++) {
            int col = hi * 64 + wn * 16 + t * 8 + gc * 2;
            float2 v0 = {accC[t][0], accC[t][1]};
            float2 v1 = {accC[t][2], accC[t][3]};
            *(float2*)&out[((size_t)(bi * Ss + rowg)) * Dd + col] = v0;
            *(float2*)&out[((size_t)(bi * Ss + rowg + 8)) * Dd + col] = v1;
        }
    }
}

// ---------------- launch ----------------------------------------------------------
extern "C" void kernel_launch(void* const* d_in, const int* in_sizes, int n_in,
                              void* d_out, int out_size)
{
    (void)in_sizes; (void)n_in; (void)out_size;
    const float* hidden = (const float*)d_in[0];
    const float* mask   = (const float*)d_in[1];
    const float* ctxemb = (const float*)d_in[2];
    const float* Wq = (const float*)d_in[3];  const float* bq = (const float*)d_in[4];
    const float* Wk = (const float*)d_in[5];  const float* bk = (const float*)d_in[6];
    const float* Wv = (const float*)d_in[7];  const float* bv = (const float*)d_in[8];
    const float* Wcq = (const float*)d_in[9]; const float* bcq = (const float*)d_in[10];
    const float* Wck = (const float*)d_in[11];const float* bck = (const float*)d_in[12];
    const float* wlqc = (const float*)d_in[13];
    const float* wlqq = (const float*)d_in[14];
    const float* wlkc = (const float*)d_in[15];
    const float* wlkk = (const float*)d_in[16];
    float* out = (float*)d_out;

    cudaFuncSetAttribute(attn_fused, cudaFuncAttributeMaxDynamicSharedMemorySize, ATTN_SMEM);

    // user launch index 3 = attn_fused (profiled by ncu)
    cqck_mma<<<32, 256>>>(ctxemb, Wcq, bcq, Wck, bck);                        // 0
    qsig_kernel<<<dim3(16, 16, Bb), 256>>>(mask);                             // 1
    proj_mma<<<dim3(8, 32, 3), 256>>>(hidden, Wq, Wk, Wv, bq, bk, bv);        // 2
    attn_fused<<<dim3(32, 64), 256, ATTN_SMEM>>>(mask, out, wlqc, wlqq, wlkc, wlkk); // 3
}

// round 14
// speedup vs baseline: 1.1327x; 1.1327x over previous
#include <cuda_runtime.h>
#include <cuda_bf16.h>
#include <cuda_fp16.h>
#include <cstdint>

#define Bb 4
#define Ss 1024
#define Dd 1024
#define Hh 16
#define DHh 64
#define SCALE 0.125f

// ---------------- scratch (device globals; no allocation allowed) ----------------
__device__ uint32_t g_Qt[Bb * Hh * Ss * DHh]; // tf32 bits [b][h][s][d]
__device__ uint32_t g_Kt[Bb * Hh * Ss * DHh];
__device__ uint32_t g_Vt[Bb * Hh * Ss * DHh];
__device__ float g_CQ[Bb * Ss * DHh];
__device__ float g_CK[Bb * Ss * DHh];
__device__ float g_qsig[Bb * Ss * Ss];        // sigmoid quasi scores (head-invariant)
__device__ uint32_t g_Atf[Bb * Ss * Dd];      // tf32 hidden
__device__ uint32_t g_Wtf[3 * Dd * Dd];       // tf32 Wq|Wk|Wv

__device__ __forceinline__ float sigmoidf_(float x) { return 1.0f / (1.0f + __expf(-x)); }

__device__ __forceinline__ uint32_t f2tf(float x) {
    uint32_t r; asm("cvt.rna.tf32.f32 %0, %1;" : "=r"(r) : "f"(x)); return r;
}

__device__ __forceinline__ void mma_tf32(float* d, const uint32_t* a, const uint32_t* b) {
    asm volatile(
        "mma.sync.aligned.m16n8k8.row.col.f32.tf32.tf32.f32 "
        "{%0,%1,%2,%3}, {%4,%5,%6,%7}, {%8,%9}, {%0,%1,%2,%3};"
        : "+f"(d[0]), "+f"(d[1]), "+f"(d[2]), "+f"(d[3])
        : "r"(a[0]), "r"(a[1]), "r"(a[2]), "r"(a[3]), "r"(b[0]), "r"(b[1]));
}

__device__ __forceinline__ void cpa16(void* dst, const void* src) {
    uint32_t sa = (uint32_t)__cvta_generic_to_shared(dst);
    asm volatile("cp.async.cg.shared.global [%0], [%1], 16;" :: "r"(sa), "l"(src));
}

// ---------------- kernel 0: wide-grid tf32 conversion -----------------------------
__global__ __launch_bounds__(256) void conv_tf32(
    const float* __restrict__ hidden,
    const float* __restrict__ Wq, const float* __restrict__ Wk, const float* __restrict__ Wv)
{
    const int NT = gridDim.x * 256;
    const int t0 = blockIdx.x * 256 + threadIdx.x;
    const float4* hs = (const float4*)hidden;
    uint4* ad = (uint4*)g_Atf;
    for (int i = t0; i < (Bb * Ss * Dd) / 4; i += NT) {
        float4 v = hs[i];
        uint4 t = {f2tf(v.x), f2tf(v.y), f2tf(v.z), f2tf(v.w)};
        ad[i] = t;
    }
    const float* Ws[3] = {Wq, Wk, Wv};
#pragma unroll
    for (int wsel = 0; wsel < 3; wsel++) {
        const float4* s = (const float4*)Ws[wsel];
        uint4* d = (uint4*)(g_Wtf + wsel * (Dd * Dd));
        for (int i = t0; i < (Dd * Dd) / 4; i += NT) {
            float4 v = s[i];
            uint4 t = {f2tf(v.x), f2tf(v.y), f2tf(v.z), f2tf(v.w)};
            d[i] = t;
        }
    }
}

// ---------------- kernel 1: tf32 MMA CQ|CK GEMM -----------------------------------
__global__ __launch_bounds__(256, 2) void cqck_mma(
    const float* __restrict__ A,
    const float* __restrict__ Wcq, const float* __restrict__ bcq,
    const float* __restrict__ Wck, const float* __restrict__ bck)
{
    __shared__ uint32_t As[128][36];
    __shared__ uint32_t Bs[32][132];

    const int bm = blockIdx.x;
    const int tid = threadIdx.x;
    const int warpId = tid >> 5, lane = tid & 31;
    const int warpM = warpId & 1, warpN = warpId >> 1;
    const int gr = lane >> 2, gc = lane & 3;

    float acc[4][4][4];
#pragma unroll
    for (int i = 0; i < 4; i++)
#pragma unroll
        for (int j = 0; j < 4; j++)
#pragma unroll
            for (int t = 0; t < 4; t++) acc[i][j][t] = 0.0f;

    for (int k0 = 0; k0 < 1024; k0 += 32) {
#pragma unroll
        for (int i = 0; i < 4; i++) {
            int idx = tid + i * 256;
            int r = idx >> 3, c4 = idx & 7;
            float4 v = *(const float4*)&A[(size_t)(bm * 128 + r) * 1024 + k0 + c4 * 4];
            uint4 t = {f2tf(v.x), f2tf(v.y), f2tf(v.z), f2tf(v.w)};
            *(uint4*)&As[r][c4 * 4] = t;
        }
#pragma unroll
        for (int i = 0; i < 4; i++) {
            int idx = tid + i * 256;
            int row = idx >> 5;
            int c4  = idx & 31;
            int col = c4 * 4;
            const float* src = (col < 64)
                ? &Wcq[(size_t)(k0 + row) * 64 + col]
                : &Wck[(size_t)(k0 + row) * 64 + (col - 64)];
            float4 v = *(const float4*)src;
            uint4 t = {f2tf(v.x), f2tf(v.y), f2tf(v.z), f2tf(v.w)};
            *(uint4*)&Bs[row][col] = t;
        }
        __syncthreads();

#pragma unroll
        for (int ks = 0; ks < 4; ks++) {
            const int kb = ks * 8;
            uint32_t af[4][4];
#pragma unroll
            for (int mt = 0; mt < 4; mt++) {
                int m = warpM * 64 + mt * 16;
                af[mt][0] = As[m + gr][kb + gc];
                af[mt][1] = As[m + gr + 8][kb + gc];
                af[mt][2] = As[m + gr][kb + gc + 4];
                af[mt][3] = As[m + gr + 8][kb + gc + 4];
            }
            uint32_t bf[4][2];
#pragma unroll
            for (int nt = 0; nt < 4; nt++) {
                int n = warpN * 32 + nt * 8 + gr;
                bf[nt][0] = Bs[kb + gc][n];
                bf[nt][1] = Bs[kb + gc + 4][n];
            }
#pragma unroll
            for (int mt = 0; mt < 4; mt++)
#pragma unroll
                for (int nt = 0; nt < 4; nt++)
                    mma_tf32(acc[mt][nt], af[mt], bf[nt]);
        }
        __syncthreads();
    }

#pragma unroll
    for (int mt = 0; mt < 4; mt++) {
        int m0 = bm * 128 + warpM * 64 + mt * 16 + gr;
#pragma unroll
        for (int half = 0; half < 2; half++) {
            int m = m0 + half * 8;
#pragma unroll
            for (int nt = 0; nt < 4; nt++) {
                int n = warpN * 32 + nt * 8 + gc * 2;
                float2 v;
                if (n < 64) {
                    v.x = acc[mt][nt][half * 2 + 0] + bcq[n];
                    v.y = acc[mt][nt][half * 2 + 1] + bcq[n + 1];
                    *(float2*)&g_CQ[(size_t)m * 64 + n] = v;
                } else {
                    v.x = acc[mt][nt][half * 2 + 0] + bck[n - 64];
                    v.y = acc[mt][nt][half * 2 + 1] + bck[n - 63];
                    *(float2*)&g_CK[(size_t)m * 64 + (n - 64)] = v;
                }
            }
        }
    }
}

// ---------------- kernel 2: head-invariant quasi sigmoid [B,S,S] ------------------
__global__ __launch_bounds__(256) void qsig_kernel(const float* __restrict__ mask)
{
    __shared__ float Qs[64 * 68];
    __shared__ float Ks[64 * 68];
    const int bi = blockIdx.z, qt = blockIdx.y, kt = blockIdx.x;
    const int tid = threadIdx.x;
    const int tx = tid & 15, ty = tid >> 4;

#pragma unroll
    for (int i = 0; i < 4; i++) {
        int idx = tid + i * 256;
        int m = idx >> 4, c4 = idx & 15;
        float4 vq = *(const float4*)&g_CQ[((size_t)(bi * Ss + qt * 64 + m)) * 64 + c4 * 4];
        float4 vk = *(const float4*)&g_CK[((size_t)(bi * Ss + kt * 64 + m)) * 64 + c4 * 4];
        Qs[(c4 * 4 + 0) * 68 + m] = vq.x; Qs[(c4 * 4 + 1) * 68 + m] = vq.y;
        Qs[(c4 * 4 + 2) * 68 + m] = vq.z; Qs[(c4 * 4 + 3) * 68 + m] = vq.w;
        Ks[(c4 * 4 + 0) * 68 + m] = vk.x; Ks[(c4 * 4 + 1) * 68 + m] = vk.y;
        Ks[(c4 * 4 + 2) * 68 + m] = vk.z; Ks[(c4 * 4 + 3) * 68 + m] = vk.w;
    }
    __syncthreads();

    float acc[4][4];
#pragma unroll
    for (int i = 0; i < 4; i++)
#pragma unroll
        for (int j = 0; j < 4; j++) acc[i][j] = 0.0f;

#pragma unroll 4
    for (int d = 0; d < 64; d++) {
        float4 a4 = *(float4*)&Qs[d * 68 + ty * 4];
        float4 b4 = *(float4*)&Ks[d * 68 + tx * 4];
        float a[4] = {a4.x, a4.y, a4.z, a4.w};
        float bv[4] = {b4.x, b4.y, b4.z, b4.w};
#pragma unroll
        for (int i = 0; i < 4; i++)
#pragma unroll
            for (int j = 0; j < 4; j++) acc[i][j] += a[i] * bv[j];
    }
#pragma unroll
    for (int i = 0; i < 4; i++) {
        int qrow = qt * 64 + ty * 4 + i;
#pragma unroll
        for (int j = 0; j < 4; j++) {
            int kcol = kt * 64 + tx * 4 + j;
            float v = sigmoidf_(acc[i][j] * SCALE + mask[bi * Ss + kcol]);
            g_qsig[((size_t)(bi * Ss + qrow)) * Ss + kcol] = v;
        }
    }
}

// ---------------- kernel 3: pipelined tf32 projection GEMM (QKV, grid z=3) --------
#define PROJ_SMEM ((2 * 128 * 36 + 2 * 32 * 132) * 4)

__global__ __launch_bounds__(256, 2) void proj_mma(
    const float* __restrict__ bq, const float* __restrict__ bk, const float* __restrict__ bv)
{
    extern __shared__ uint32_t ps[];
    uint32_t* As = ps;                 // 2 stages: [st][128][36]
    uint32_t* Bs = ps + 2 * 128 * 36;  // 2 stages: [st][32][132]

    const int which = blockIdx.z;
    const uint32_t* Wtf = g_Wtf + which * (Dd * Dd);
    const float* bias = (which == 0) ? bq : (which == 1) ? bk : bv;
    uint32_t* outt = (which == 0) ? g_Qt : (which == 1) ? g_Kt : g_Vt;

    const int bm = blockIdx.y, bn = blockIdx.x;
    const int tid = threadIdx.x;
    const int warpId = tid >> 5, lane = tid & 31;
    const int warpM = warpId & 1, warpN = warpId >> 1;
    const int gr = lane >> 2, gc = lane & 3;

    float acc[4][4][4];
#pragma unroll
    for (int i = 0; i < 4; i++)
#pragma unroll
        for (int j = 0; j < 4; j++)
#pragma unroll
            for (int t = 0; t < 4; t++) acc[i][j][t] = 0.0f;

    auto issue = [&](int st, int k0) {
#pragma unroll
        for (int i = 0; i < 4; i++) {
            int idx = tid + i * 256;
            int r = idx >> 3, c4 = idx & 7;
            cpa16(&As[st * 4608 + r * 36 + c4 * 4],
                  &g_Atf[(size_t)(bm * 128 + r) * 1024 + k0 + c4 * 4]);
        }
#pragma unroll
        for (int i = 0; i < 4; i++) {
            int idx = tid + i * 256;
            int row = idx >> 5, c4 = idx & 31;
            cpa16(&Bs[st * 4224 + row * 132 + c4 * 4],
                  &Wtf[(size_t)(k0 + row) * 1024 + bn * 128 + c4 * 4]);
        }
        asm volatile("cp.async.commit_group;");
    };

    issue(0, 0);

    for (int kt = 0; kt < 32; kt++) {
        if (kt < 31) {
            issue((kt + 1) & 1, (kt + 1) * 32);
            asm volatile("cp.async.wait_group 1;");
        } else {
            asm volatile("cp.async.wait_group 0;");
        }
        __syncthreads();

        const uint32_t* Ast = As + (kt & 1) * 4608;
        const uint32_t* Bst = Bs + (kt & 1) * 4224;
#pragma unroll
        for (int ks = 0; ks < 4; ks++) {
            const int kb = ks * 8;
            uint32_t af[4][4];
#pragma unroll
            for (int mt = 0; mt < 4; mt++) {
                int m = warpM * 64 + mt * 16;
                af[mt][0] = Ast[(m + gr) * 36 + kb + gc];
                af[mt][1] = Ast[(m + gr + 8) * 36 + kb + gc];
                af[mt][2] = Ast[(m + gr) * 36 + kb + gc + 4];
                af[mt][3] = Ast[(m + gr + 8) * 36 + kb + gc + 4];
            }
            uint32_t bf[4][2];
#pragma unroll
            for (int nt = 0; nt < 4; nt++) {
                int n = warpN * 32 + nt * 8 + gr;
                bf[nt][0] = Bst[(kb + gc) * 132 + n];
                bf[nt][1] = Bst[(kb + gc + 4) * 132 + n];
            }
#pragma unroll
            for (int mt = 0; mt < 4; mt++)
#pragma unroll
                for (int nt = 0; nt < 4; nt++)
                    mma_tf32(acc[mt][nt], af[mt], bf[nt]);
        }
        __syncthreads();
    }

    // epilogue: scatter tf32 bits to [B,H,S,DH]
#pragma unroll
    for (int mt = 0; mt < 4; mt++) {
        int m0 = bm * 128 + warpM * 64 + mt * 16 + gr;
#pragma unroll
        for (int half = 0; half < 2; half++) {
            int m = m0 + half * 8;
            int b = m >> 10, s = m & 1023;
#pragma unroll
            for (int nt = 0; nt < 4; nt++) {
                int n = bn * 128 + warpN * 32 + nt * 8 + gc * 2;
                int h = n >> 6, d = n & 63;
                size_t o = (((size_t)(b * Hh + h) * Ss + s)) * 64 + d;
                uint2 tv = {f2tf(acc[mt][nt][half * 2 + 0] + bias[n]),
                            f2tf(acc[mt][nt][half * 2 + 1] + bias[n + 1])};
                *(uint2*)&outt[o] = tv;
            }
        }
    }
}

// ---------------- kernel 4: attention A+B, one-pass, fp16 exp buffer --------------
#define SC_H 1040
#define ATTN_SMEM (128 * 68 * 4 + 32 * 68 * 4 + 32 * SC_H * 2 + (32 * 4 + 32 + 32) * 4)

__global__ __launch_bounds__(256, 2) void attn_ab(
    const float* __restrict__ mask, float* __restrict__ out,
    const float* __restrict__ wlqc, const float* __restrict__ wlqq,
    const float* __restrict__ wlkc, const float* __restrict__ wlkk)
{
    extern __shared__ uint32_t smu[];
    uint32_t* Ks  = smu;                         // 128*68 u32
    uint32_t* Qtf = Ks + 128 * 68;               // 32*68 u32
    __half* Sc    = (__half*)(Qtf + 32 * 68);    // 32*1040 half
    float* red    = (float*)(Sc + 32 * SC_H);    // [32][4]
    float* inv_s  = red + 32 * 4;                // 32
    float* lam_s  = inv_s + 32;                  // 32

    const int qb = blockIdx.x;
    const int bh = blockIdx.y;
    const int bi = bh >> 4;
    const int tid = threadIdx.x;
    const int w = tid >> 5, lane = tid & 31;
    const int gr = lane >> 2, gc = lane & 3;
    const int wm = w >> 2, wn = w & 3;           // 2m x 4n warp grid

    const uint32_t* Qtg = &g_Qt[((size_t)bh * Ss + qb * 32) * 64];
    const uint32_t* Ktg = &g_Kt[(size_t)bh * Ss * 64];
    const float* maskb = &mask[bi * Ss];

    const size_t OFF_NEW   = (size_t)Bb * Ss * Dd;
    const size_t OFF_PROBS = OFF_NEW + (size_t)Bb * Hh * Ss * Ss;
    const size_t OFF_QUASI = OFF_PROBS + (size_t)Bb * Hh * Ss * Ss;

    // load Q tile [32][64] tf32 bits
#pragma unroll
    for (int i = 0; i < 2; i++) {
        int idx = tid + i * 256;
        int m = idx >> 4, c4 = idx & 15;
        uint4 v = *(const uint4*)&Qtg[(size_t)m * 64 + c4 * 4];
        *(uint4*)&Qtf[m * 68 + c4 * 4] = v;
    }

    // lambda_context (tf32 bits reinterpret as fp32; 8 threads per row)
    {
        int r = tid >> 3;          // 0..31
        int j = tid & 7;           // 0..7
        int qrow = qb * 32 + r;
        const float* cq = &g_CQ[((size_t)(bi * Ss + qrow)) * 64];
        const float* ck = &g_CK[((size_t)(bi * Ss + qrow)) * 64];
        const uint32_t* qp = &g_Qt[((size_t)bh * Ss + qrow) * 64];
        const uint32_t* kp = &g_Kt[((size_t)bh * Ss + qrow) * 64];
        float sq = 0.f, sk = 0.f;
#pragma unroll
        for (int d0 = 0; d0 < 8; d0++) {
            int d = j * 8 + d0;
            sq += cq[d] * wlqc[d] + __uint_as_float(qp[d]) * wlqq[d];
            sk += ck[d] * wlkc[d] + __uint_as_float(kp[d]) * wlkk[d];
        }
#pragma unroll
        for (int o = 4; o > 0; o >>= 1) {
            sq += __shfl_xor_sync(0xffffffffu, sq, o);
            sk += __shfl_xor_sync(0xffffffffu, sk, o);
        }
        if (j == 0) lam_s[r] = 1.0f - sigmoidf_(sq) - sigmoidf_(sk);
    }

    const int row0 = wm * 16 + gr;          // this thread's rows: row0, row0+8
    float rsum0 = 0.0f, rsum1 = 0.0f;

    // ---------- Phase A: scores -> exp -> half Sc, accumulate row sums ----------
    for (int nt = 0; nt < 8; nt++) {
#pragma unroll
        for (int i = 0; i < 8; i++) {
            int idx = tid + i * 256;          // 0..2047
            int n = idx >> 4, c4 = idx & 15;
            uint4 v = *(const uint4*)&Ktg[((size_t)(nt * 128 + n)) * 64 + c4 * 4];
            *(uint4*)&Ks[n * 68 + c4 * 4] = v;
        }
        __syncthreads();

        float acc[4][4];
#pragma unroll
        for (int t = 0; t < 4; t++)
#pragma unroll
            for (int e = 0; e < 4; e++) acc[t][e] = 0.0f;

#pragma unroll
        for (int ks = 0; ks < 8; ks++) {
            const int kb = ks * 8;
            uint32_t af[4];
            af[0] = Qtf[(wm * 16 + gr) * 68 + kb + gc];
            af[1] = Qtf[(wm * 16 + gr + 8) * 68 + kb + gc];
            af[2] = Qtf[(wm * 16 + gr) * 68 + kb + gc + 4];
            af[3] = Qtf[(wm * 16 + gr + 8) * 68 + kb + gc + 4];
#pragma unroll
            for (int t = 0; t < 4; t++) {
                int n0 = wn * 32 + t * 8;
                uint32_t bf[2];
                bf[0] = Ks[(n0 + gr) * 68 + kb + gc];
                bf[1] = Ks[(n0 + gr) * 68 + kb + gc + 4];
                mma_tf32(acc[t], af, bf);
            }
        }

#pragma unroll
        for (int t = 0; t < 4; t++) {
            int col = nt * 128 + wn * 32 + t * 8 + gc * 2;
            float mk0 = maskb[col], mk1 = maskb[col + 1];
            float e00 = __expf(acc[t][0] * SCALE + mk0);
            float e01 = __expf(acc[t][1] * SCALE + mk1);
            float e10 = __expf(acc[t][2] * SCALE + mk0);
            float e11 = __expf(acc[t][3] * SCALE + mk1);
            rsum0 += e00 + e01;
            rsum1 += e10 + e11;
            *(__half2*)&Sc[row0 * SC_H + col] = __floats2half2_rn(e00, e01);
            *(__half2*)&Sc[(row0 + 8) * SC_H + col] = __floats2half2_rn(e10, e11);
        }
        __syncthreads();
    }

    // reduce sums: over gc lanes, then across the 4 n-warps
    rsum0 += __shfl_xor_sync(0xffffffffu, rsum0, 1);
    rsum0 += __shfl_xor_sync(0xffffffffu, rsum0, 2);
    rsum1 += __shfl_xor_sync(0xffffffffu, rsum1, 1);
    rsum1 += __shfl_xor_sync(0xffffffffu, rsum1, 2);
    if (gc == 0) {
        red[row0 * 4 + wn] = rsum0;
        red[(row0 + 8) * 4 + wn] = rsum1;
    }
    __syncthreads();
    if (tid < 32) {
        float s = red[tid * 4] + red[tid * 4 + 1] + red[tid * 4 + 2] + red[tid * 4 + 3];
        inv_s[tid] = 1.0f / s;
    }
    __syncthreads();

    // ---------- Phase B: stream probs/quasi/new from Sc (half) ----------
    for (int r = w * 4; r < w * 4 + 4; r++) {
        const float inv = inv_s[r];
        const float lam = lam_s[r];
        const int qrow = qb * 32 + r;
        const float* qs_row = &g_qsig[((size_t)(bi * Ss + qrow)) * Ss];
        const size_t rowbase = ((size_t)bh * Ss + qrow) * Ss;
        float* probs_row = out + OFF_PROBS + rowbase;
        float* quasi_row = out + OFF_QUASI + rowbase;
        float* new_row   = out + OFF_NEW + rowbase;

        for (int c8 = lane; c8 < 128; c8 += 32) {
            int col = c8 * 8;
            uint4 hv = *(uint4*)&Sc[r * SC_H + col];
            const __half2* hp = (const __half2*)&hv;
            float2 e01 = __half22float2(hp[0]);
            float2 e23 = __half22float2(hp[1]);
            float2 e45 = __half22float2(hp[2]);
            float2 e67 = __half22float2(hp[3]);
            float4 p0 = {e01.x * inv, e01.y * inv, e23.x * inv, e23.y * inv};
            float4 p1 = {e45.x * inv, e45.y * inv, e67.x * inv, e67.y * inv};
            float4 qs0 = *(const float4*)&qs_row[col];
            float4 qs1 = *(const float4*)&qs_row[col + 4];
            float4 qp0 = {lam * qs0.x, lam * qs0.y, lam * qs0.z, lam * qs0.w};
            float4 qp1 = {lam * qs1.x, lam * qs1.y, lam * qs1.z, lam * qs1.w};
            float4 n0 = {p0.x + qp0.x, p0.y + qp0.y, p0.z + qp0.z, p0.w + qp0.w};
            float4 n1 = {p1.x + qp1.x, p1.y + qp1.y, p1.z + qp1.z, p1.w + qp1.w};
            *(float4*)&probs_row[col] = p0;     *(float4*)&probs_row[col + 4] = p1;
            *(float4*)&quasi_row[col] = qp0;    *(float4*)&quasi_row[col + 4] = qp1;
            *(float4*)&new_row[col] = n0;       *(float4*)&new_row[col + 4] = n1;
        }
    }
}

// ---------------- kernel 5: ctx = newP @ V, cp.async 2-stage ----------------------
#define PV_SMEM ((2 * 128 * 36 + 2 * 32 * 72) * 4)

__global__ __launch_bounds__(256) void pv_gemm(float* __restrict__ out)
{
    extern __shared__ uint32_t pvs[];
    float*    Psf = (float*)pvs;            // 2 x 128*36
    uint32_t* Vs  = pvs + 2 * 128 * 36;     // 2 x 32*72

    const int qt = blockIdx.x;
    const int bh = blockIdx.y;
    const int bi = bh >> 4, hi = bh & 15;
    const int tid = threadIdx.x;
    const int warpId = tid >> 5, lane = tid & 31;
    const int wm = warpId & 3, wn = warpId >> 2;
    const int gr = lane >> 2, gc = lane & 3;

    const size_t OFF_NEW = (size_t)Bb * Ss * Dd;
    const float* newb = out + OFF_NEW + ((size_t)bh * Ss + qt * 128) * Ss;
    const uint32_t* Vtg = &g_Vt[(size_t)bh * Ss * 64];

    float acc[2][4][4];
#pragma unroll
    for (int m = 0; m < 2; m++)
#pragma unroll
        for (int t = 0; t < 4; t++)
#pragma unroll
            for (int e = 0; e < 4; e++) acc[m][t][e] = 0.0f;

    auto issue = [&](int st, int kt) {
#pragma unroll
        for (int i = 0; i < 4; i++) {
            int idx = tid + i * 256;
            int r = idx >> 3, c4 = idx & 7;
            cpa16(&Psf[st * 4608 + r * 36 + c4 * 4],
                  &newb[(size_t)r * 1024 + kt * 32 + c4 * 4]);
        }
#pragma unroll
        for (int i = 0; i < 2; i++) {
            int idx = tid + i * 256;
            int k = idx >> 4, c4 = idx & 15;
            cpa16(&Vs[st * 2304 + k * 72 + c4 * 4],
                  &Vtg[((size_t)(kt * 32 + k)) * 64 + c4 * 4]);
        }
        asm volatile("cp.async.commit_group;");
    };

    issue(0, 0);

    for (int kt = 0; kt < 32; kt++) {
        if (kt < 31) {
            issue((kt + 1) & 1, kt + 1);
            asm volatile("cp.async.wait_group 1;");
        } else {
            asm volatile("cp.async.wait_group 0;");
        }
        __syncthreads();

        const float* Pst = Psf + (kt & 1) * 4608;
        const uint32_t* Vst = Vs + (kt & 1) * 2304;
#pragma unroll
        for (int ks = 0; ks < 4; ks++) {
            const int kb = ks * 8;
            uint32_t af[2][4];
#pragma unroll
            for (int m = 0; m < 2; m++) {
                int m0 = wm * 32 + m * 16;
                af[m][0] = f2tf(Pst[(m0 + gr) * 36 + kb + gc]);
                af[m][1] = f2tf(Pst[(m0 + gr + 8) * 36 + kb + gc]);
                af[m][2] = f2tf(Pst[(m0 + gr) * 36 + kb + gc + 4]);
                af[m][3] = f2tf(Pst[(m0 + gr + 8) * 36 + kb + gc + 4]);
            }
#pragma unroll
            for (int t = 0; t < 4; t++) {
                int n0 = wn * 32 + t * 8;
                uint32_t bf[2];
                bf[0] = Vst[(kb + gc) * 72 + n0 + gr];
                bf[1] = Vst[(kb + gc + 4) * 72 + n0 + gr];
                mma_tf32(acc[0][t], af[0], bf);
                mma_tf32(acc[1][t], af[1], bf);
            }
        }
        __syncthreads();
    }

#pragma unroll
    for (int m = 0; m < 2; m++) {
        int row0 = qt * 128 + wm * 32 + m * 16 + gr;
#pragma unroll
        for (int t = 0; t < 4; t++) {
            int col = hi * 64 + wn * 32 + t * 8 + gc * 2;
            float2 v0 = {acc[m][t][0], acc[m][t][1]};
            float2 v1 = {acc[m][t][2], acc[m][t][3]};
            *(float2*)&out[((size_t)(bi * Ss + row0)) * Dd + col] = v0;
            *(float2*)&out[((size_t)(bi * Ss + row0 + 8)) * Dd + col] = v1;
        }
    }
}

// ---------------- launch ----------------------------------------------------------
extern "C" void kernel_launch(void* const* d_in, const int* in_sizes, int n_in,
                              void* d_out, int out_size)
{
    (void)in_sizes; (void)n_in; (void)out_size;
    const float* hidden = (const float*)d_in[0];
    const float* mask   = (const float*)d_in[1];
    const float* ctxemb = (const float*)d_in[2];
    const float* Wq = (const float*)d_in[3];  const float* bq = (const float*)d_in[4];
    const float* Wk = (const float*)d_in[5];  const float* bk = (const float*)d_in[6];
    const float* Wv = (const float*)d_in[7];  const float* bv = (const float*)d_in[8];
    const float* Wcq = (const float*)d_in[9]; const float* bcq = (const float*)d_in[10];
    const float* Wck = (const float*)d_in[11];const float* bck = (const float*)d_in[12];
    const float* wlqc = (const float*)d_in[13];
    const float* wlqq = (const float*)d_in[14];
    const float* wlkc = (const float*)d_in[15];
    const float* wlkk = (const float*)d_in[16];
    float* out = (float*)d_out;

    cudaFuncSetAttribute(proj_mma, cudaFuncAttributeMaxDynamicSharedMemorySize, PROJ_SMEM);
    cudaFuncSetAttribute(attn_ab, cudaFuncAttributeMaxDynamicSharedMemorySize, ATTN_SMEM);
    cudaFuncSetAttribute(pv_gemm, cudaFuncAttributeMaxDynamicSharedMemorySize, PV_SMEM);

    // user launch index 3 = proj_mma (profiled by ncu this round)
    conv_tf32<<<1792, 256>>>(hidden, Wq, Wk, Wv);                             // 0
    cqck_mma<<<32, 256>>>(ctxemb, Wcq, bcq, Wck, bck);                        // 1
    qsig_kernel<<<dim3(16, 16, Bb), 256>>>(mask);                             // 2
    proj_mma<<<dim3(8, 32, 3), 256, PROJ_SMEM>>>(bq, bk, bv);                 // 3
    attn_ab<<<dim3(32, 64), 256, ATTN_SMEM>>>(mask, out, wlqc, wlqq, wlkc, wlkk); // 4
    pv_gemm<<<dim3(8, 64), 256, PV_SMEM>>>(out);                              // 5
}

// round 16
// speedup vs baseline: 1.4006x; 1.2365x over previous
#include <cuda_runtime.h>
#include <cuda_bf16.h>
#include <cuda_fp16.h>
#include <cstdint>

#define Bb 4
#define Ss 1024
#define Dd 1024
#define Hh 16
#define DHh 64
#define SCALE 0.125f

// ---------------- scratch (device globals; no allocation allowed) ----------------
__device__ __half   g_Qh[Bb * Hh * Ss * DHh]; // fp16 [b][h][s][d]
__device__ __half   g_Kh[Bb * Hh * Ss * DHh];
__device__ uint32_t g_Vt[Bb * Hh * Ss * DHh]; // tf32 bits (pv_gemm path)
__device__ float g_CQ[Bb * Ss * DHh];
__device__ float g_CK[Bb * Ss * DHh];
__device__ float g_qsig[Bb * Ss * Ss];        // sigmoid quasi scores (head-invariant)
__device__ __half g_Ah[Bb * Ss * Dd];         // fp16 hidden [m][k]
__device__ __half g_WhT[3 * Dd * Dd];         // fp16 W transposed [which][n][k]

__device__ __forceinline__ float sigmoidf_(float x) { return 1.0f / (1.0f + __expf(-x)); }

__device__ __forceinline__ uint32_t f2tf(float x) {
    uint32_t r; asm("cvt.rna.tf32.f32 %0, %1;" : "=r"(r) : "f"(x)); return r;
}

__device__ __forceinline__ void mma_tf32(float* d, const uint32_t* a, const uint32_t* b) {
    asm volatile(
        "mma.sync.aligned.m16n8k8.row.col.f32.tf32.tf32.f32 "
        "{%0,%1,%2,%3}, {%4,%5,%6,%7}, {%8,%9}, {%0,%1,%2,%3};"
        : "+f"(d[0]), "+f"(d[1]), "+f"(d[2]), "+f"(d[3])
        : "r"(a[0]), "r"(a[1]), "r"(a[2]), "r"(a[3]), "r"(b[0]), "r"(b[1]));
}

__device__ __forceinline__ void mma_f16(float* d, const uint32_t* a, const uint32_t* b) {
    asm volatile(
        "mma.sync.aligned.m16n8k16.row.col.f32.f16.f16.f32 "
        "{%0,%1,%2,%3}, {%4,%5,%6,%7}, {%8,%9}, {%0,%1,%2,%3};"
        : "+f"(d[0]), "+f"(d[1]), "+f"(d[2]), "+f"(d[3])
        : "r"(a[0]), "r"(a[1]), "r"(a[2]), "r"(a[3]), "r"(b[0]), "r"(b[1]));
}

__device__ __forceinline__ void cpa16(void* dst, const void* src) {
    uint32_t sa = (uint32_t)__cvta_generic_to_shared(dst);
    asm volatile("cp.async.cg.shared.global [%0], [%1], 16;" :: "r"(sa), "l"(src));
}

// ---------------- kernel 0: convert hidden->fp16; W -> fp16 transposed ------------
__global__ __launch_bounds__(256) void conv_h(
    const float* __restrict__ hidden,
    const float* __restrict__ Wq, const float* __restrict__ Wk, const float* __restrict__ Wv)
{
    // hidden -> g_Ah (row-major half)
    {
        const int NT = gridDim.x * 256;
        int t0 = blockIdx.x * 256 + threadIdx.x;
        const float4* hs = (const float4*)hidden;
        for (int i = t0; i < (Bb * Ss * Dd) / 4; i += NT) {
            float4 v = hs[i];
            __half2 h0 = __floats2half2_rn(v.x, v.y);
            __half2 h1 = __floats2half2_rn(v.z, v.w);
            uint2 u = {*(uint32_t*)&h0, *(uint32_t*)&h1};
            *(uint2*)&g_Ah[(size_t)i * 4] = u;
        }
    }
    // W -> g_WhT[which][n][k] via tiled transpose
    __shared__ float T[32][33];
    const float* Ws[3] = {Wq, Wk, Wv};
    const int tx = threadIdx.x & 31, ty = threadIdx.x >> 5;
    for (int tile = blockIdx.x; tile < 3 * 1024; tile += gridDim.x) {
        int wsel = tile >> 10;
        int t2 = tile & 1023;
        int k0 = (t2 >> 5) * 32, n0 = (t2 & 31) * 32;
        const float* W = Ws[wsel];
        __syncthreads();
#pragma unroll
        for (int r = ty; r < 32; r += 8)
            T[r][tx] = W[(size_t)(k0 + r) * 1024 + n0 + tx];
        __syncthreads();
#pragma unroll
        for (int r = ty; r < 32; r += 8)
            g_WhT[(size_t)wsel * 1024 * 1024 + (size_t)(n0 + r) * 1024 + k0 + tx] =
                __float2half_rn(T[tx][r]);
    }
}

// ---------------- kernel 1: tf32 MMA CQ|CK GEMM -----------------------------------
__global__ __launch_bounds__(256, 2) void cqck_mma(
    const float* __restrict__ A,
    const float* __restrict__ Wcq, const float* __restrict__ bcq,
    const float* __restrict__ Wck, const float* __restrict__ bck)
{
    __shared__ uint32_t As[128][36];
    __shared__ uint32_t Bs[32][132];

    const int bm = blockIdx.x;
    const int tid = threadIdx.x;
    const int warpId = tid >> 5, lane = tid & 31;
    const int warpM = warpId & 1, warpN = warpId >> 1;
    const int gr = lane >> 2, gc = lane & 3;

    float acc[4][4][4];
#pragma unroll
    for (int i = 0; i < 4; i++)
#pragma unroll
        for (int j = 0; j < 4; j++)
#pragma unroll
            for (int t = 0; t < 4; t++) acc[i][j][t] = 0.0f;

    for (int k0 = 0; k0 < 1024; k0 += 32) {
#pragma unroll
        for (int i = 0; i < 4; i++) {
            int idx = tid + i * 256;
            int r = idx >> 3, c4 = idx & 7;
            float4 v = *(const float4*)&A[(size_t)(bm * 128 + r) * 1024 + k0 + c4 * 4];
            uint4 t = {f2tf(v.x), f2tf(v.y), f2tf(v.z), f2tf(v.w)};
            *(uint4*)&As[r][c4 * 4] = t;
        }
#pragma unroll
        for (int i = 0; i < 4; i++) {
            int idx = tid + i * 256;
            int row = idx >> 5;
            int c4  = idx & 31;
            int col = c4 * 4;
            const float* src = (col < 64)
                ? &Wcq[(size_t)(k0 + row) * 64 + col]
                : &Wck[(size_t)(k0 + row) * 64 + (col - 64)];
            float4 v = *(const float4*)src;
            uint4 t = {f2tf(v.x), f2tf(v.y), f2tf(v.z), f2tf(v.w)};
            *(uint4*)&Bs[row][col] = t;
        }
        __syncthreads();

#pragma unroll
        for (int ks = 0; ks < 4; ks++) {
            const int kb = ks * 8;
            uint32_t af[4][4];
#pragma unroll
            for (int mt = 0; mt < 4; mt++) {
                int m = warpM * 64 + mt * 16;
                af[mt][0] = As[m + gr][kb + gc];
                af[mt][1] = As[m + gr + 8][kb + gc];
                af[mt][2] = As[m + gr][kb + gc + 4];
                af[mt][3] = As[m + gr + 8][kb + gc + 4];
            }
            uint32_t bf[4][2];
#pragma unroll
            for (int nt = 0; nt < 4; nt++) {
                int n = warpN * 32 + nt * 8 + gr;
                bf[nt][0] = Bs[kb + gc][n];
                bf[nt][1] = Bs[kb + gc + 4][n];
            }
#pragma unroll
            for (int mt = 0; mt < 4; mt++)
#pragma unroll
                for (int nt = 0; nt < 4; nt++)
                    mma_tf32(acc[mt][nt], af[mt], bf[nt]);
        }
        __syncthreads();
    }

#pragma unroll
    for (int mt = 0; mt < 4; mt++) {
        int m0 = bm * 128 + warpM * 64 + mt * 16 + gr;
#pragma unroll
        for (int half = 0; half < 2; half++) {
            int m = m0 + half * 8;
#pragma unroll
            for (int nt = 0; nt < 4; nt++) {
                int n = warpN * 32 + nt * 8 + gc * 2;
                float2 v;
                if (n < 64) {
                    v.x = acc[mt][nt][half * 2 + 0] + bcq[n];
                    v.y = acc[mt][nt][half * 2 + 1] + bcq[n + 1];
                    *(float2*)&g_CQ[(size_t)m * 64 + n] = v;
                } else {
                    v.x = acc[mt][nt][half * 2 + 0] + bck[n - 64];
                    v.y = acc[mt][nt][half * 2 + 1] + bck[n - 63];
                    *(float2*)&g_CK[(size_t)m * 64 + (n - 64)] = v;
                }
            }
        }
    }
}

// ---------------- kernel 2: head-invariant quasi sigmoid [B,S,S] ------------------
__global__ __launch_bounds__(256) void qsig_kernel(const float* __restrict__ mask)
{
    __shared__ float Qs[64 * 68];
    __shared__ float Ks[64 * 68];
    const int bi = blockIdx.z, qt = blockIdx.y, kt = blockIdx.x;
    const int tid = threadIdx.x;
    const int tx = tid & 15, ty = tid >> 4;

#pragma unroll
    for (int i = 0; i < 4; i++) {
        int idx = tid + i * 256;
        int m = idx >> 4, c4 = idx & 15;
        float4 vq = *(const float4*)&g_CQ[((size_t)(bi * Ss + qt * 64 + m)) * 64 + c4 * 4];
        float4 vk = *(const float4*)&g_CK[((size_t)(bi * Ss + kt * 64 + m)) * 64 + c4 * 4];
        Qs[(c4 * 4 + 0) * 68 + m] = vq.x; Qs[(c4 * 4 + 1) * 68 + m] = vq.y;
        Qs[(c4 * 4 + 2) * 68 + m] = vq.z; Qs[(c4 * 4 + 3) * 68 + m] = vq.w;
        Ks[(c4 * 4 + 0) * 68 + m] = vk.x; Ks[(c4 * 4 + 1) * 68 + m] = vk.y;
        Ks[(c4 * 4 + 2) * 68 + m] = vk.z; Ks[(c4 * 4 + 3) * 68 + m] = vk.w;
    }
    __syncthreads();

    float acc[4][4];
#pragma unroll
    for (int i = 0; i < 4; i++)
#pragma unroll
        for (int j = 0; j < 4; j++) acc[i][j] = 0.0f;

#pragma unroll 4
    for (int d = 0; d < 64; d++) {
        float4 a4 = *(float4*)&Qs[d * 68 + ty * 4];
        float4 b4 = *(float4*)&Ks[d * 68 + tx * 4];
        float a[4] = {a4.x, a4.y, a4.z, a4.w};
        float bv[4] = {b4.x, b4.y, b4.z, b4.w};
#pragma unroll
        for (int i = 0; i < 4; i++)
#pragma unroll
            for (int j = 0; j < 4; j++) acc[i][j] += a[i] * bv[j];
    }
#pragma unroll
    for (int i = 0; i < 4; i++) {
        int qrow = qt * 64 + ty * 4 + i;
#pragma unroll
        for (int j = 0; j < 4; j++) {
            int kcol = kt * 64 + tx * 4 + j;
            float v = sigmoidf_(acc[i][j] * SCALE + mask[bi * Ss + kcol]);
            g_qsig[((size_t)(bi * Ss + qrow)) * Ss + kcol] = v;
        }
    }
}

// ---------------- kernel 3: fp16 projection GEMM, cp.async 2-stage, grid z=3 ------
// As [2][128][40] half, Bs [2][128][40] half (WhT tile [n][k]) -> 40960 B
#define PROJ_SMEM ((2 * 128 * 40 + 2 * 128 * 40) * 2)

__global__ __launch_bounds__(256, 2) void proj_h(
    const float* __restrict__ bq, const float* __restrict__ bk, const float* __restrict__ bv)
{
    extern __shared__ __half phs[];
    __half* As = phs;                   // 2 stages x 128 x 40
    __half* Bs = phs + 2 * 128 * 40;

    const int which = blockIdx.z;
    const __half* WhT = g_WhT + (size_t)which * 1024 * 1024;
    const float* bias = (which == 0) ? bq : (which == 1) ? bk : bv;

    const int bm = blockIdx.y, bn = blockIdx.x;
    const int tid = threadIdx.x;
    const int warpId = tid >> 5, lane = tid & 31;
    const int warpM = warpId & 1, warpN = warpId >> 1;
    const int gr = lane >> 2, gc = lane & 3;

    float acc[4][4][4];
#pragma unroll
    for (int i = 0; i < 4; i++)
#pragma unroll
        for (int j = 0; j < 4; j++)
#pragma unroll
            for (int t = 0; t < 4; t++) acc[i][j][t] = 0.0f;

    auto issue = [&](int st, int k0) {
#pragma unroll
        for (int i = 0; i < 2; i++) {
            int idx = tid + i * 256;          // 0..511
            int r = idx >> 2, c8 = idx & 3;
            cpa16(&As[st * 5120 + r * 40 + c8 * 8],
                  &g_Ah[(size_t)(bm * 128 + r) * 1024 + k0 + c8 * 8]);
        }
#pragma unroll
        for (int i = 0; i < 2; i++) {
            int idx = tid + i * 256;
            int n = idx >> 2, c8 = idx & 3;
            cpa16(&Bs[st * 5120 + n * 40 + c8 * 8],
                  &WhT[(size_t)(bn * 128 + n) * 1024 + k0 + c8 * 8]);
        }
        asm volatile("cp.async.commit_group;");
    };

    issue(0, 0);

    for (int kt = 0; kt < 32; kt++) {
        if (kt < 31) {
            issue((kt + 1) & 1, (kt + 1) * 32);
            asm volatile("cp.async.wait_group 1;");
        } else {
            asm volatile("cp.async.wait_group 0;");
        }
        __syncthreads();

        const __half* Ast = As + (kt & 1) * 5120;
        const __half* Bst = Bs + (kt & 1) * 5120;
#pragma unroll
        for (int ks = 0; ks < 2; ks++) {
            const int kb = ks * 16;
            uint32_t af[4][4];
#pragma unroll
            for (int mt = 0; mt < 4; mt++) {
                int m = warpM * 64 + mt * 16;
                af[mt][0] = *(const uint32_t*)&Ast[(m + gr) * 40 + kb + 2 * gc];
                af[mt][1] = *(const uint32_t*)&Ast[(m + gr + 8) * 40 + kb + 2 * gc];
                af[mt][2] = *(const uint32_t*)&Ast[(m + gr) * 40 + kb + 2 * gc + 8];
                af[mt][3] = *(const uint32_t*)&Ast[(m + gr + 8) * 40 + kb + 2 * gc + 8];
            }
            uint32_t bf[4][2];
#pragma unroll
            for (int nt = 0; nt < 4; nt++) {
                int n = warpN * 32 + nt * 8 + gr;
                bf[nt][0] = *(const uint32_t*)&Bst[n * 40 + kb + 2 * gc];
                bf[nt][1] = *(const uint32_t*)&Bst[n * 40 + kb + 2 * gc + 8];
            }
#pragma unroll
            for (int mt = 0; mt < 4; mt++)
#pragma unroll
                for (int nt = 0; nt < 4; nt++)
                    mma_f16(acc[mt][nt], af[mt], bf[nt]);
        }
        __syncthreads();
    }

    // epilogue: scatter to [B,H,S,DH]; Q/K as fp16, V as tf32 bits
#pragma unroll
    for (int mt = 0; mt < 4; mt++) {
        int m0 = bm * 128 + warpM * 64 + mt * 16 + gr;
#pragma unroll
        for (int half_ = 0; half_ < 2; half_++) {
            int m = m0 + half_ * 8;
            int b = m >> 10, s = m & 1023;
#pragma unroll
            for (int nt = 0; nt < 4; nt++) {
                int n = bn * 128 + warpN * 32 + nt * 8 + gc * 2;
                int h = n >> 6, d = n & 63;
                size_t o = (((size_t)(b * Hh + h) * Ss + s)) * 64 + d;
                float vx = acc[mt][nt][half_ * 2 + 0] + bias[n];
                float vy = acc[mt][nt][half_ * 2 + 1] + bias[n + 1];
                if (which == 0) {
                    *(__half2*)&g_Qh[o] = __floats2half2_rn(vx, vy);
                } else if (which == 1) {
                    *(__half2*)&g_Kh[o] = __floats2half2_rn(vx, vy);
                } else {
                    uint2 tv = {f2tf(vx), f2tf(vy)};
                    *(uint2*)&g_Vt[o] = tv;
                }
            }
        }
    }
}

// ---------------- kernel 4: attention A+B, fp16 MMA, fp16 exp buffer --------------
// smem: Ks[256][72]h (36864B) + Qh[32][72]h (4608B) + Sc[32][1040]h (66560B) + 768B
#define SC_H 1040
#define ATTN_SMEM (256 * 72 * 2 + 32 * 72 * 2 + 32 * SC_H * 2 + (32 * 4 + 32 + 32) * 4)

__global__ __launch_bounds__(256, 2) void attn_ab(
    const float* __restrict__ mask, float* __restrict__ out,
    const float* __restrict__ wlqc, const float* __restrict__ wlqq,
    const float* __restrict__ wlkc, const float* __restrict__ wlkk)
{
    extern __shared__ __half smh[];
    __half* Ksm = smh;                           // 256*72
    __half* Qsm = Ksm + 256 * 72;                // 32*72
    __half* Sc  = Qsm + 32 * 72;                 // 32*1040
    float* red   = (float*)(Sc + 32 * SC_H);     // [32][4]
    float* inv_s = red + 32 * 4;                 // 32
    float* lam_s = inv_s + 32;                   // 32

    const int qb = blockIdx.x;
    const int bh = blockIdx.y;
    const int bi = bh >> 4;
    const int tid = threadIdx.x;
    const int w = tid >> 5, lane = tid & 31;
    const int gr = lane >> 2, gc = lane & 3;
    const int wm = w >> 2, wn = w & 3;           // 2m x 4n warp grid

    const __half* Qg = &g_Qh[((size_t)bh * Ss + qb * 32) * 64];
    const __half* Kg = &g_Kh[(size_t)bh * Ss * 64];
    const float* maskb = &mask[bi * Ss];

    const size_t OFF_NEW   = (size_t)Bb * Ss * Dd;
    const size_t OFF_PROBS = OFF_NEW + (size_t)Bb * Hh * Ss * Ss;
    const size_t OFF_QUASI = OFF_PROBS + (size_t)Bb * Hh * Ss * Ss;

    // load Q tile [32][64] fp16 (one 16B chunk per thread)
    {
        int m = tid >> 3, c8 = tid & 7;
        uint4 v = *(const uint4*)&Qg[(size_t)m * 64 + c8 * 8];
        *(uint4*)&Qsm[m * 72 + c8 * 8] = v;
    }

    // lambda_context (fp16 q/k; 8 threads per row)
    {
        int r = tid >> 3;          // 0..31
        int j = tid & 7;           // 0..7
        int qrow = qb * 32 + r;
        const float* cq = &g_CQ[((size_t)(bi * Ss + qrow)) * 64];
        const float* ck = &g_CK[((size_t)(bi * Ss + qrow)) * 64];
        const __half* qp = &g_Qh[((size_t)bh * Ss + qrow) * 64];
        const __half* kp = &g_Kh[((size_t)bh * Ss + qrow) * 64];
        float sq = 0.f, sk = 0.f;
#pragma unroll
        for (int d0 = 0; d0 < 8; d0++) {
            int d = j * 8 + d0;
            sq += cq[d] * wlqc[d] + __half2float(qp[d]) * wlqq[d];
            sk += ck[d] * wlkc[d] + __half2float(kp[d]) * wlkk[d];
        }
#pragma unroll
        for (int o = 4; o > 0; o >>= 1) {
            sq += __shfl_xor_sync(0xffffffffu, sq, o);
            sk += __shfl_xor_sync(0xffffffffu, sk, o);
        }
        if (j == 0) lam_s[r] = 1.0f - sigmoidf_(sq) - sigmoidf_(sk);
    }

    const int row0 = wm * 16 + gr;          // this thread's rows: row0, row0+8
    float rsum0 = 0.0f, rsum1 = 0.0f;

    // ---------- Phase A: fp16 MMA scores -> exp -> half Sc, row sums ----------
    for (int nt = 0; nt < 4; nt++) {
        // K chunk: 256 rows x 64 d fp16 (8 chunks of 8 halfs per row)
#pragma unroll
        for (int i = 0; i < 8; i++) {
            int idx = tid + i * 256;          // 0..2047
            int n = idx >> 3, c8 = idx & 7;
            uint4 v = *(const uint4*)&Kg[((size_t)(nt * 256 + n)) * 64 + c8 * 8];
            *(uint4*)&Ksm[n * 72 + c8 * 8] = v;
        }
        __syncthreads();

        float acc[8][4];
#pragma unroll
        for (int t = 0; t < 8; t++)
#pragma unroll
            for (int e = 0; e < 4; e++) acc[t][e] = 0.0f;

#pragma unroll
        for (int ks = 0; ks < 4; ks++) {
            const int kb = ks * 16;
            uint32_t af[4];
            af[0] = *(const uint32_t*)&Qsm[(wm * 16 + gr) * 72 + kb + 2 * gc];
            af[1] = *(const uint32_t*)&Qsm[(wm * 16 + gr + 8) * 72 + kb + 2 * gc];
            af[2] = *(const uint32_t*)&Qsm[(wm * 16 + gr) * 72 + kb + 2 * gc + 8];
            af[3] = *(const uint32_t*)&Qsm[(wm * 16 + gr + 8) * 72 + kb + 2 * gc + 8];
#pragma unroll
            for (int t = 0; t < 8; t++) {
                int n0 = wn * 64 + t * 8;
                uint32_t bf[2];
                bf[0] = *(const uint32_t*)&Ksm[(n0 + gr) * 72 + kb + 2 * gc];
                bf[1] = *(const uint32_t*)&Ksm[(n0 + gr) * 72 + kb + 2 * gc + 8];
                mma_f16(acc[t], af, bf);
            }
        }

#pragma unroll
        for (int t = 0; t < 8; t++) {
            int col = nt * 256 + wn * 64 + t * 8 + gc * 2;
            float mk0 = maskb[col], mk1 = maskb[col + 1];
            float e00 = __expf(acc[t][0] * SCALE + mk0);
            float e01 = __expf(acc[t][1] * SCALE + mk1);
            float e10 = __expf(acc[t][2] * SCALE + mk0);
            float e11 = __expf(acc[t][3] * SCALE + mk1);
            rsum0 += e00 + e01;
            rsum1 += e10 + e11;
            *(__half2*)&Sc[row0 * SC_H + col] = __floats2half2_rn(e00, e01);
            *(__half2*)&Sc[(row0 + 8) * SC_H + col] = __floats2half2_rn(e10, e11);
        }
        __syncthreads();
    }

    // reduce sums: over gc lanes, then across the 4 n-warps
    rsum0 += __shfl_xor_sync(0xffffffffu, rsum0, 1);
    rsum0 += __shfl_xor_sync(0xffffffffu, rsum0, 2);
    rsum1 += __shfl_xor_sync(0xffffffffu, rsum1, 1);
    rsum1 += __shfl_xor_sync(0xffffffffu, rsum1, 2);
    if (gc == 0) {
        red[row0 * 4 + wn] = rsum0;
        red[(row0 + 8) * 4 + wn] = rsum1;
    }
    __syncthreads();
    if (tid < 32) {
        float s = red[tid * 4] + red[tid * 4 + 1] + red[tid * 4 + 2] + red[tid * 4 + 3];
        inv_s[tid] = 1.0f / s;
    }
    __syncthreads();

    // ---------- Phase B: stream probs/quasi/new from Sc (half) ----------
    for (int r = w * 4; r < w * 4 + 4; r++) {
        const float inv = inv_s[r];
        const float lam = lam_s[r];
        const int qrow = qb * 32 + r;
        const float* qs_row = &g_qsig[((size_t)(bi * Ss + qrow)) * Ss];
        const size_t rowbase = ((size_t)bh * Ss + qrow) * Ss;
        float* probs_row = out + OFF_PROBS + rowbase;
        float* quasi_row = out + OFF_QUASI + rowbase;
        float* new_row   = out + OFF_NEW + rowbase;

        for (int c8 = lane; c8 < 128; c8 += 32) {
            int col = c8 * 8;
            uint4 hv = *(uint4*)&Sc[r * SC_H + col];
            const __half2* hp = (const __half2*)&hv;
            float2 e01 = __half22float2(hp[0]);
            float2 e23 = __half22float2(hp[1]);
            float2 e45 = __half22float2(hp[2]);
            float2 e67 = __half22float2(hp[3]);
            float4 p0 = {e01.x * inv, e01.y * inv, e23.x * inv, e23.y * inv};
            float4 p1 = {e45.x * inv, e45.y * inv, e67.x * inv, e67.y * inv};
            float4 qs0 = *(const float4*)&qs_row[col];
            float4 qs1 = *(const float4*)&qs_row[col + 4];
            float4 qp0 = {lam * qs0.x, lam * qs0.y, lam * qs0.z, lam * qs0.w};
            float4 qp1 = {lam * qs1.x, lam * qs1.y, lam * qs1.z, lam * qs1.w};
            float4 n0 = {p0.x + qp0.x, p0.y + qp0.y, p0.z + qp0.z, p0.w + qp0.w};
            float4 n1 = {p1.x + qp1.x, p1.y + qp1.y, p1.z + qp1.z, p1.w + qp1.w};
            *(float4*)&probs_row[col] = p0;     *(float4*)&probs_row[col + 4] = p1;
            *(float4*)&quasi_row[col] = qp0;    *(float4*)&quasi_row[col + 4] = qp1;
            *(float4*)&new_row[col] = n0;       *(float4*)&new_row[col + 4] = n1;
        }
    }
}

// ---------------- kernel 5: ctx = newP @ V, cp.async 2-stage (tf32) ---------------
#define PV_SMEM ((2 * 128 * 36 + 2 * 32 * 72) * 4)

__global__ __launch_bounds__(256) void pv_gemm(float* __restrict__ out)
{
    extern __shared__ uint32_t pvs[];
    float*    Psf = (float*)pvs;            // 2 x 128*36
    uint32_t* Vs  = pvs + 2 * 128 * 36;     // 2 x 32*72

    const int qt = blockIdx.x;
    const int bh = blockIdx.y;
    const int bi = bh >> 4, hi = bh & 15;
    const int tid = threadIdx.x;
    const int warpId = tid >> 5, lane = tid & 31;
    const int wm = warpId & 3, wn = warpId >> 2;
    const int gr = lane >> 2, gc = lane & 3;

    const size_t OFF_NEW = (size_t)Bb * Ss * Dd;
    const float* newb = out + OFF_NEW + ((size_t)bh * Ss + qt * 128) * Ss;
    const uint32_t* Vtg = &g_Vt[(size_t)bh * Ss * 64];

    float acc[2][4][4];
#pragma unroll
    for (int m = 0; m < 2; m++)
#pragma unroll
        for (int t = 0; t < 4; t++)
#pragma unroll
            for (int e = 0; e < 4; e++) acc[m][t][e] = 0.0f;

    auto issue = [&](int st, int kt) {
#pragma unroll
        for (int i = 0; i < 4; i++) {
            int idx = tid + i * 256;
            int r = idx >> 3, c4 = idx & 7;
            cpa16(&Psf[st * 4608 + r * 36 + c4 * 4],
                  &newb[(size_t)r * 1024 + kt * 32 + c4 * 4]);
        }
#pragma unroll
        for (int i = 0; i < 2; i++) {
            int idx = tid + i * 256;
            int k = idx >> 4, c4 = idx & 15;
            cpa16(&Vs[st * 2304 + k * 72 + c4 * 4],
                  &Vtg[((size_t)(kt * 32 + k)) * 64 + c4 * 4]);
        }
        asm volatile("cp.async.commit_group;");
    };

    issue(0, 0);

    for (int kt = 0; kt < 32; kt++) {
        if (kt < 31) {
            issue((kt + 1) & 1, kt + 1);
            asm volatile("cp.async.wait_group 1;");
        } else {
            asm volatile("cp.async.wait_group 0;");
        }
        __syncthreads();

        const float* Pst = Psf + (kt & 1) * 4608;
        const uint32_t* Vst = Vs + (kt & 1) * 2304;
#pragma unroll
        for (int ks = 0; ks < 4; ks++) {
            const int kb = ks * 8;
            uint32_t af[2][4];
#pragma unroll
            for (int m = 0; m < 2; m++) {
                int m0 = wm * 32 + m * 16;
                af[m][0] = f2tf(Pst[(m0 + gr) * 36 + kb + gc]);
                af[m][1] = f2tf(Pst[(m0 + gr + 8) * 36 + kb + gc]);
                af[m][2] = f2tf(Pst[(m0 + gr) * 36 + kb + gc + 4]);
                af[m][3] = f2tf(Pst[(m0 + gr + 8) * 36 + kb + gc + 4]);
            }
#pragma unroll
            for (int t = 0; t < 4; t++) {
                int n0 = wn * 32 + t * 8;
                uint32_t bf[2];
                bf[0] = Vst[(kb + gc) * 72 + n0 + gr];
                bf[1] = Vst[(kb + gc + 4) * 72 + n0 + gr];
                mma_tf32(acc[0][t], af[0], bf);
                mma_tf32(acc[1][t], af[1], bf);
            }
        }
        __syncthreads();
    }

#pragma unroll
    for (int m = 0; m < 2; m++) {
        int row0 = qt * 128 + wm * 32 + m * 16 + gr;
#pragma unroll
        for (int t = 0; t < 4; t++) {
            int col = hi * 64 + wn * 32 + t * 8 + gc * 2;
            float2 v0 = {acc[m][t][0], acc[m][t][1]};
            float2 v1 = {acc[m][t][2], acc[m][t][3]};
            *(float2*)&out[((size_t)(bi * Ss + row0)) * Dd + col] = v0;
            *(float2*)&out[((size_t)(bi * Ss + row0 + 8)) * Dd + col] = v1;
        }
    }
}

// ---------------- launch ----------------------------------------------------------
extern "C" void kernel_launch(void* const* d_in, const int* in_sizes, int n_in,
                              void* d_out, int out_size)
{
    (void)in_sizes; (void)n_in; (void)out_size;
    const float* hidden = (const float*)d_in[0];
    const float* mask   = (const float*)d_in[1];
    const float* ctxemb = (const float*)d_in[2];
    const float* Wq = (const float*)d_in[3];  const float* bq = (const float*)d_in[4];
    const float* Wk = (const float*)d_in[5];  const float* bk = (const float*)d_in[6];
    const float* Wv = (const float*)d_in[7];  const float* bv = (const float*)d_in[8];
    const float* Wcq = (const float*)d_in[9]; const float* bcq = (const float*)d_in[10];
    const float* Wck = (const float*)d_in[11];const float* bck = (const float*)d_in[12];
    const float* wlqc = (const float*)d_in[13];
    const float* wlqq = (const float*)d_in[14];
    const float* wlkc = (const float*)d_in[15];
    const float* wlkk = (const float*)d_in[16];
    float* out = (float*)d_out;

    cudaFuncSetAttribute(proj_h, cudaFuncAttributeMaxDynamicSharedMemorySize, PROJ_SMEM);
    cudaFuncSetAttribute(attn_ab, cudaFuncAttributeMaxDynamicSharedMemorySize, ATTN_SMEM);
    cudaFuncSetAttribute(pv_gemm, cudaFuncAttributeMaxDynamicSharedMemorySize, PV_SMEM);

    // user launch index 3 = proj_h (profiled by ncu this round)
    conv_h<<<1792, 256>>>(hidden, Wq, Wk, Wv);                                // 0
    cqck_mma<<<32, 256>>>(ctxemb, Wcq, bcq, Wck, bck);                        // 1
    qsig_kernel<<<dim3(16, 16, Bb), 256>>>(mask);                             // 2
    proj_h<<<dim3(8, 32, 3), 256, PROJ_SMEM>>>(bq, bk, bv);                   // 3
    attn_ab<<<dim3(32, 64), 256, ATTN_SMEM>>>(mask, out, wlqc, wlqq, wlkc, wlkk); // 4
    pv_gemm<<<dim3(8, 64), 256, PV_SMEM>>>(out);                              // 5
}

// round 17
// speedup vs baseline: 1.4107x; 1.0072x over previous
#include <cuda_runtime.h>
#include <cuda_bf16.h>
#include <cuda_fp16.h>
#include <cstdint>

#define Bb 4
#define Ss 1024
#define Dd 1024
#define Hh 16
#define DHh 64
#define SCALE 0.125f

// ---------------- scratch (device globals; no allocation allowed) ----------------
__device__ __half   g_Qh[Bb * Hh * Ss * DHh]; // fp16 [b][h][s][d]
__device__ __half   g_Kh[Bb * Hh * Ss * DHh];
__device__ uint32_t g_Vt[Bb * Hh * Ss * DHh]; // tf32 bits (pv_gemm path)
__device__ float g_CQ[Bb * Ss * DHh];
__device__ float g_CK[Bb * Ss * DHh];
__device__ float g_qsig[Bb * Ss * Ss];        // sigmoid quasi scores (head-invariant)
__device__ __half g_Ah[Bb * Ss * Dd];         // fp16 hidden [m][k]
__device__ __half g_WhT[3 * Dd * Dd];         // fp16 W transposed [which][n][k]

__device__ __forceinline__ float sigmoidf_(float x) { return 1.0f / (1.0f + __expf(-x)); }

__device__ __forceinline__ uint32_t f2tf(float x) {
    uint32_t r; asm("cvt.rna.tf32.f32 %0, %1;" : "=r"(r) : "f"(x)); return r;
}

__device__ __forceinline__ void mma_tf32(float* d, const uint32_t* a, const uint32_t* b) {
    asm volatile(
        "mma.sync.aligned.m16n8k8.row.col.f32.tf32.tf32.f32 "
        "{%0,%1,%2,%3}, {%4,%5,%6,%7}, {%8,%9}, {%0,%1,%2,%3};"
        : "+f"(d[0]), "+f"(d[1]), "+f"(d[2]), "+f"(d[3])
        : "r"(a[0]), "r"(a[1]), "r"(a[2]), "r"(a[3]), "r"(b[0]), "r"(b[1]));
}

__device__ __forceinline__ void mma_f16(float* d, const uint32_t* a, const uint32_t* b) {
    asm volatile(
        "mma.sync.aligned.m16n8k16.row.col.f32.f16.f16.f32 "
        "{%0,%1,%2,%3}, {%4,%5,%6,%7}, {%8,%9}, {%0,%1,%2,%3};"
        : "+f"(d[0]), "+f"(d[1]), "+f"(d[2]), "+f"(d[3])
        : "r"(a[0]), "r"(a[1]), "r"(a[2]), "r"(a[3]), "r"(b[0]), "r"(b[1]));
}

__device__ __forceinline__ void cpa16(void* dst, const void* src) {
    uint32_t sa = (uint32_t)__cvta_generic_to_shared(dst);
    asm volatile("cp.async.cg.shared.global [%0], [%1], 16;" :: "r"(sa), "l"(src));
}

// ---------------- kernel 0: merged conversion + CQ/CK GEMM ------------------------
// blocks 0..31: cqck tf32 MMA GEMM; blocks 32..: hidden->fp16 + W transpose->fp16.
__global__ __launch_bounds__(256) void conv_cqck(
    const float* __restrict__ hidden,
    const float* __restrict__ Wq, const float* __restrict__ Wk, const float* __restrict__ Wv,
    const float* __restrict__ A,
    const float* __restrict__ Wcq, const float* __restrict__ bcq,
    const float* __restrict__ Wck, const float* __restrict__ bck)
{
    __shared__ uint32_t smbuf[128 * 36 + 32 * 132];   // cqck As|Bs; conv reuses as T
    const int tid = threadIdx.x;

    if (blockIdx.x >= 32) {
        // ---- conversion path ----
        const int cb = blockIdx.x - 32;
        const int CNB = gridDim.x - 32;
        {
            const int NT = CNB * 256;
            int t0 = cb * 256 + tid;
            const float4* hs = (const float4*)hidden;
            for (int i = t0; i < (Bb * Ss * Dd) / 4; i += NT) {
                float4 v = hs[i];
                __half2 h0 = __floats2half2_rn(v.x, v.y);
                __half2 h1 = __floats2half2_rn(v.z, v.w);
                uint2 u = {*(uint32_t*)&h0, *(uint32_t*)&h1};
                *(uint2*)&g_Ah[(size_t)i * 4] = u;
            }
        }
        float* T = (float*)smbuf;                      // 32*33 floats
        const float* Ws[3] = {Wq, Wk, Wv};
        const int tx = tid & 31, ty = tid >> 5;
        for (int tile = cb; tile < 3 * 1024; tile += gridDim.x - 32) {
            int wsel = tile >> 10;
            int t2 = tile & 1023;
            int k0 = (t2 >> 5) * 32, n0 = (t2 & 31) * 32;
            const float* W = Ws[wsel];
            __syncthreads();
#pragma unroll
            for (int r = ty; r < 32; r += 8)
                T[r * 33 + tx] = W[(size_t)(k0 + r) * 1024 + n0 + tx];
            __syncthreads();
#pragma unroll
            for (int r = ty; r < 32; r += 8)
                g_WhT[(size_t)wsel * 1024 * 1024 + (size_t)(n0 + r) * 1024 + k0 + tx] =
                    __float2half_rn(T[tx * 33 + r]);
        }
        return;
    }

    // ---- cqck path (tf32 MMA), flat-indexed smem ----
    uint32_t* As = smbuf;             // [128][36]
    uint32_t* Bs = smbuf + 128 * 36;  // [32][132]

    const int bm = blockIdx.x;
    const int warpId = tid >> 5, lane = tid & 31;
    const int warpM = warpId & 1, warpN = warpId >> 1;
    const int gr = lane >> 2, gc = lane & 3;

    float acc[4][4][4];
#pragma unroll
    for (int i = 0; i < 4; i++)
#pragma unroll
        for (int j = 0; j < 4; j++)
#pragma unroll
            for (int t = 0; t < 4; t++) acc[i][j][t] = 0.0f;

    for (int k0 = 0; k0 < 1024; k0 += 32) {
#pragma unroll
        for (int i = 0; i < 4; i++) {
            int idx = tid + i * 256;
            int r = idx >> 3, c4 = idx & 7;
            float4 v = *(const float4*)&A[(size_t)(bm * 128 + r) * 1024 + k0 + c4 * 4];
            uint4 t = {f2tf(v.x), f2tf(v.y), f2tf(v.z), f2tf(v.w)};
            *(uint4*)&As[r * 36 + c4 * 4] = t;
        }
#pragma unroll
        for (int i = 0; i < 4; i++) {
            int idx = tid + i * 256;
            int row = idx >> 5;
            int c4  = idx & 31;
            int col = c4 * 4;
            const float* src = (col < 64)
                ? &Wcq[(size_t)(k0 + row) * 64 + col]
                : &Wck[(size_t)(k0 + row) * 64 + (col - 64)];
            float4 v = *(const float4*)src;
            uint4 t = {f2tf(v.x), f2tf(v.y), f2tf(v.z), f2tf(v.w)};
            *(uint4*)&Bs[row * 132 + col] = t;
        }
        __syncthreads();

#pragma unroll
        for (int ks = 0; ks < 4; ks++) {
            const int kb = ks * 8;
            uint32_t af[4][4];
#pragma unroll
            for (int mt = 0; mt < 4; mt++) {
                int m = warpM * 64 + mt * 16;
                af[mt][0] = As[(m + gr) * 36 + kb + gc];
                af[mt][1] = As[(m + gr + 8) * 36 + kb + gc];
                af[mt][2] = As[(m + gr) * 36 + kb + gc + 4];
                af[mt][3] = As[(m + gr + 8) * 36 + kb + gc + 4];
            }
            uint32_t bf[4][2];
#pragma unroll
            for (int nt = 0; nt < 4; nt++) {
                int n = warpN * 32 + nt * 8 + gr;
                bf[nt][0] = Bs[(kb + gc) * 132 + n];
                bf[nt][1] = Bs[(kb + gc + 4) * 132 + n];
            }
#pragma unroll
            for (int mt = 0; mt < 4; mt++)
#pragma unroll
                for (int nt = 0; nt < 4; nt++)
                    mma_tf32(acc[mt][nt], af[mt], bf[nt]);
        }
        __syncthreads();
    }

#pragma unroll
    for (int mt = 0; mt < 4; mt++) {
        int m0 = bm * 128 + warpM * 64 + mt * 16 + gr;
#pragma unroll
        for (int half_ = 0; half_ < 2; half_++) {
            int m = m0 + half_ * 8;
#pragma unroll
            for (int nt = 0; nt < 4; nt++) {
                int n = warpN * 32 + nt * 8 + gc * 2;
                float2 v;
                if (n < 64) {
                    v.x = acc[mt][nt][half_ * 2 + 0] + bcq[n];
                    v.y = acc[mt][nt][half_ * 2 + 1] + bcq[n + 1];
                    *(float2*)&g_CQ[(size_t)m * 64 + n] = v;
                } else {
                    v.x = acc[mt][nt][half_ * 2 + 0] + bck[n - 64];
                    v.y = acc[mt][nt][half_ * 2 + 1] + bck[n - 63];
                    *(float2*)&g_CK[(size_t)m * 64 + (n - 64)] = v;
                }
            }
        }
    }
}

// ---------------- kernel 1: head-invariant quasi sigmoid [B,S,S] ------------------
__global__ __launch_bounds__(256) void qsig_kernel(const float* __restrict__ mask)
{
    __shared__ float Qs[64 * 68];
    __shared__ float Ks[64 * 68];
    const int bi = blockIdx.z, qt = blockIdx.y, kt = blockIdx.x;
    const int tid = threadIdx.x;
    const int tx = tid & 15, ty = tid >> 4;

#pragma unroll
    for (int i = 0; i < 4; i++) {
        int idx = tid + i * 256;
        int m = idx >> 4, c4 = idx & 15;
        float4 vq = *(const float4*)&g_CQ[((size_t)(bi * Ss + qt * 64 + m)) * 64 + c4 * 4];
        float4 vk = *(const float4*)&g_CK[((size_t)(bi * Ss + kt * 64 + m)) * 64 + c4 * 4];
        Qs[(c4 * 4 + 0) * 68 + m] = vq.x; Qs[(c4 * 4 + 1) * 68 + m] = vq.y;
        Qs[(c4 * 4 + 2) * 68 + m] = vq.z; Qs[(c4 * 4 + 3) * 68 + m] = vq.w;
        Ks[(c4 * 4 + 0) * 68 + m] = vk.x; Ks[(c4 * 4 + 1) * 68 + m] = vk.y;
        Ks[(c4 * 4 + 2) * 68 + m] = vk.z; Ks[(c4 * 4 + 3) * 68 + m] = vk.w;
    }
    __syncthreads();

    float acc[4][4];
#pragma unroll
    for (int i = 0; i < 4; i++)
#pragma unroll
        for (int j = 0; j < 4; j++) acc[i][j] = 0.0f;

#pragma unroll 4
    for (int d = 0; d < 64; d++) {
        float4 a4 = *(float4*)&Qs[d * 68 + ty * 4];
        float4 b4 = *(float4*)&Ks[d * 68 + tx * 4];
        float a[4] = {a4.x, a4.y, a4.z, a4.w};
        float bv[4] = {b4.x, b4.y, b4.z, b4.w};
#pragma unroll
        for (int i = 0; i < 4; i++)
#pragma unroll
            for (int j = 0; j < 4; j++) acc[i][j] += a[i] * bv[j];
    }
#pragma unroll
    for (int i = 0; i < 4; i++) {
        int qrow = qt * 64 + ty * 4 + i;
#pragma unroll
        for (int j = 0; j < 4; j++) {
            int kcol = kt * 64 + tx * 4 + j;
            float v = sigmoidf_(acc[i][j] * SCALE + mask[bi * Ss + kcol]);
            g_qsig[((size_t)(bi * Ss + qrow)) * Ss + kcol] = v;
        }
    }
}

// ---------------- kernel 2: fp16 projection GEMM, cp.async 2-stage, grid z=3 ------
#define PROJ_SMEM ((2 * 128 * 40 + 2 * 128 * 40) * 2)

__global__ __launch_bounds__(256, 2) void proj_h(
    const float* __restrict__ bq, const float* __restrict__ bk, const float* __restrict__ bv)
{
    extern __shared__ __half phs[];
    __half* As = phs;                   // 2 stages x 128 x 40
    __half* Bs = phs + 2 * 128 * 40;

    const int which = blockIdx.z;
    const __half* WhT = g_WhT + (size_t)which * 1024 * 1024;
    const float* bias = (which == 0) ? bq : (which == 1) ? bk : bv;

    const int bm = blockIdx.y, bn = blockIdx.x;
    const int tid = threadIdx.x;
    const int warpId = tid >> 5, lane = tid & 31;
    const int warpM = warpId & 1, warpN = warpId >> 1;
    const int gr = lane >> 2, gc = lane & 3;

    float acc[4][4][4];
#pragma unroll
    for (int i = 0; i < 4; i++)
#pragma unroll
        for (int j = 0; j < 4; j++)
#pragma unroll
            for (int t = 0; t < 4; t++) acc[i][j][t] = 0.0f;

    auto issue = [&](int st, int k0) {
#pragma unroll
        for (int i = 0; i < 2; i++) {
            int idx = tid + i * 256;
            int r = idx >> 2, c8 = idx & 3;
            cpa16(&As[st * 5120 + r * 40 + c8 * 8],
                  &g_Ah[(size_t)(bm * 128 + r) * 1024 + k0 + c8 * 8]);
        }
#pragma unroll
        for (int i = 0; i < 2; i++) {
            int idx = tid + i * 256;
            int n = idx >> 2, c8 = idx & 3;
            cpa16(&Bs[st * 5120 + n * 40 + c8 * 8],
                  &WhT[(size_t)(bn * 128 + n) * 1024 + k0 + c8 * 8]);
        }
        asm volatile("cp.async.commit_group;");
    };

    issue(0, 0);

    for (int kt = 0; kt < 32; kt++) {
        if (kt < 31) {
            issue((kt + 1) & 1, (kt + 1) * 32);
            asm volatile("cp.async.wait_group 1;");
        } else {
            asm volatile("cp.async.wait_group 0;");
        }
        __syncthreads();

        const __half* Ast = As + (kt & 1) * 5120;
        const __half* Bst = Bs + (kt & 1) * 5120;
#pragma unroll
        for (int ks = 0; ks < 2; ks++) {
            const int kb = ks * 16;
            uint32_t af[4][4];
#pragma unroll
            for (int mt = 0; mt < 4; mt++) {
                int m = warpM * 64 + mt * 16;
                af[mt][0] = *(const uint32_t*)&Ast[(m + gr) * 40 + kb + 2 * gc];
                af[mt][1] = *(const uint32_t*)&Ast[(m + gr + 8) * 40 + kb + 2 * gc];
                af[mt][2] = *(const uint32_t*)&Ast[(m + gr) * 40 + kb + 2 * gc + 8];
                af[mt][3] = *(const uint32_t*)&Ast[(m + gr + 8) * 40 + kb + 2 * gc + 8];
            }
            uint32_t bf[4][2];
#pragma unroll
            for (int nt = 0; nt < 4; nt++) {
                int n = warpN * 32 + nt * 8 + gr;
                bf[nt][0] = *(const uint32_t*)&Bst[n * 40 + kb + 2 * gc];
                bf[nt][1] = *(const uint32_t*)&Bst[n * 40 + kb + 2 * gc + 8];
            }
#pragma unroll
            for (int mt = 0; mt < 4; mt++)
#pragma unroll
                for (int nt = 0; nt < 4; nt++)
                    mma_f16(acc[mt][nt], af[mt], bf[nt]);
        }
        __syncthreads();
    }

#pragma unroll
    for (int mt = 0; mt < 4; mt++) {
        int m0 = bm * 128 + warpM * 64 + mt * 16 + gr;
#pragma unroll
        for (int half_ = 0; half_ < 2; half_++) {
            int m = m0 + half_ * 8;
            int b = m >> 10, s = m & 1023;
#pragma unroll
            for (int nt = 0; nt < 4; nt++) {
                int n = bn * 128 + warpN * 32 + nt * 8 + gc * 2;
                int h = n >> 6, d = n & 63;
                size_t o = (((size_t)(b * Hh + h) * Ss + s)) * 64 + d;
                float vx = acc[mt][nt][half_ * 2 + 0] + bias[n];
                float vy = acc[mt][nt][half_ * 2 + 1] + bias[n + 1];
                if (which == 0) {
                    *(__half2*)&g_Qh[o] = __floats2half2_rn(vx, vy);
                } else if (which == 1) {
                    *(__half2*)&g_Kh[o] = __floats2half2_rn(vx, vy);
                } else {
                    uint2 tv = {f2tf(vx), f2tf(vy)};
                    *(uint2*)&g_Vt[o] = tv;
                }
            }
        }
    }
}

// ---------------- kernel 3: attention A+B, fp16 MMA, cp.async K pipeline ----------
// smem: Ks 2 stages x [128][72]h (36864B) + Qsm[32][72]h (4608B) + Sc[32][1040]h
//       (66560B) + 768B reduce  = 108800 B -> 2 blocks/SM.
#define SC_H 1040
#define KS_STG (128 * 72)
#define ATTN_SMEM (2 * KS_STG * 2 + 32 * 72 * 2 + 32 * SC_H * 2 + (32 * 4 + 32 + 32) * 4)

__global__ __launch_bounds__(256, 2) void attn_ab(
    const float* __restrict__ mask, float* __restrict__ out,
    const float* __restrict__ wlqc, const float* __restrict__ wlqq,
    const float* __restrict__ wlkc, const float* __restrict__ wlkk)
{
    extern __shared__ __half smh[];
    __half* Ksm = smh;                           // 2 x 128*72
    __half* Qsm = Ksm + 2 * KS_STG;              // 32*72
    __half* Sc  = Qsm + 32 * 72;                 // 32*1040
    float* red   = (float*)(Sc + 32 * SC_H);     // [32][4]
    float* inv_s = red + 32 * 4;                 // 32
    float* lam_s = inv_s + 32;                   // 32

    const int qb = blockIdx.x;
    const int bh = blockIdx.y;
    const int bi = bh >> 4;
    const int tid = threadIdx.x;
    const int w = tid >> 5, lane = tid & 31;
    const int gr = lane >> 2, gc = lane & 3;
    const int wm = w >> 2, wn = w & 3;           // 2m x 4n warp grid

    const __half* Qg = &g_Qh[((size_t)bh * Ss + qb * 32) * 64];
    const __half* Kg = &g_Kh[(size_t)bh * Ss * 64];
    const float* maskb = &mask[bi * Ss];

    const size_t OFF_NEW   = (size_t)Bb * Ss * Dd;
    const size_t OFF_PROBS = OFF_NEW + (size_t)Bb * Hh * Ss * Ss;
    const size_t OFF_QUASI = OFF_PROBS + (size_t)Bb * Hh * Ss * Ss;

    // issue K chunk nt (128 rows) into stage st
    auto issueK = [&](int st, int nt) {
#pragma unroll
        for (int i = 0; i < 4; i++) {
            int idx = tid + i * 256;          // 0..1023
            int n = idx >> 3, c8 = idx & 7;
            cpa16(&Ksm[st * KS_STG + n * 72 + c8 * 8],
                  &Kg[((size_t)(nt * 128 + n)) * 64 + c8 * 8]);
        }
        asm volatile("cp.async.commit_group;");
    };

    issueK(0, 0);

    // load Q tile [32][64] fp16 (one 16B chunk per thread)
    {
        int m = tid >> 3, c8 = tid & 7;
        uint4 v = *(const uint4*)&Qg[(size_t)m * 64 + c8 * 8];
        *(uint4*)&Qsm[m * 72 + c8 * 8] = v;
    }

    // lambda_context (fp16 q/k; 8 threads per row)
    {
        int r = tid >> 3;          // 0..31
        int j = tid & 7;           // 0..7
        int qrow = qb * 32 + r;
        const float* cq = &g_CQ[((size_t)(bi * Ss + qrow)) * 64];
        const float* ck = &g_CK[((size_t)(bi * Ss + qrow)) * 64];
        const __half* qp = &g_Qh[((size_t)bh * Ss + qrow) * 64];
        const __half* kp = &g_Kh[((size_t)bh * Ss + qrow) * 64];
        float sq = 0.f, sk = 0.f;
#pragma unroll
        for (int d0 = 0; d0 < 8; d0++) {
            int d = j * 8 + d0;
            sq += cq[d] * wlqc[d] + __half2float(qp[d]) * wlqq[d];
            sk += ck[d] * wlkc[d] + __half2float(kp[d]) * wlkk[d];
        }
#pragma unroll
        for (int o = 4; o > 0; o >>= 1) {
            sq += __shfl_xor_sync(0xffffffffu, sq, o);
            sk += __shfl_xor_sync(0xffffffffu, sk, o);
        }
        if (j == 0) lam_s[r] = 1.0f - sigmoidf_(sq) - sigmoidf_(sk);
    }

    const int row0 = wm * 16 + gr;          // this thread's rows: row0, row0+8
    float rsum0 = 0.0f, rsum1 = 0.0f;

    // ---------- Phase A: 8 chunks of 128 K rows, double-buffered ----------
    for (int nt = 0; nt < 8; nt++) {
        if (nt < 7) {
            issueK((nt + 1) & 1, nt + 1);
            asm volatile("cp.async.wait_group 1;");
        } else {
            asm volatile("cp.async.wait_group 0;");
        }
        __syncthreads();

        const __half* Kst = Ksm + (nt & 1) * KS_STG;
        float acc[4][4];
#pragma unroll
        for (int t = 0; t < 4; t++)
#pragma unroll
            for (int e = 0; e < 4; e++) acc[t][e] = 0.0f;

#pragma unroll
        for (int ks = 0; ks < 4; ks++) {
            const int kb = ks * 16;
            uint32_t af[4];
            af[0] = *(const uint32_t*)&Qsm[(wm * 16 + gr) * 72 + kb + 2 * gc];
            af[1] = *(const uint32_t*)&Qsm[(wm * 16 + gr + 8) * 72 + kb + 2 * gc];
            af[2] = *(const uint32_t*)&Qsm[(wm * 16 + gr) * 72 + kb + 2 * gc + 8];
            af[3] = *(const uint32_t*)&Qsm[(wm * 16 + gr + 8) * 72 + kb + 2 * gc + 8];
#pragma unroll
            for (int t = 0; t < 4; t++) {
                int n0 = wn * 32 + t * 8;
                uint32_t bf[2];
                bf[0] = *(const uint32_t*)&Kst[(n0 + gr) * 72 + kb + 2 * gc];
                bf[1] = *(const uint32_t*)&Kst[(n0 + gr) * 72 + kb + 2 * gc + 8];
                mma_f16(acc[t], af, bf);
            }
        }

#pragma unroll
        for (int t = 0; t < 4; t++) {
            int col = nt * 128 + wn * 32 + t * 8 + gc * 2;
            float mk0 = maskb[col], mk1 = maskb[col + 1];
            float e00 = __expf(acc[t][0] * SCALE + mk0);
            float e01 = __expf(acc[t][1] * SCALE + mk1);
            float e10 = __expf(acc[t][2] * SCALE + mk0);
            float e11 = __expf(acc[t][3] * SCALE + mk1);
            rsum0 += e00 + e01;
            rsum1 += e10 + e11;
            *(__half2*)&Sc[row0 * SC_H + col] = __floats2half2_rn(e00, e01);
            *(__half2*)&Sc[(row0 + 8) * SC_H + col] = __floats2half2_rn(e10, e11);
        }
        __syncthreads();   // protect stage reuse by next issue
    }

    // reduce sums: over gc lanes, then across the 4 n-warps
    rsum0 += __shfl_xor_sync(0xffffffffu, rsum0, 1);
    rsum0 += __shfl_xor_sync(0xffffffffu, rsum0, 2);
    rsum1 += __shfl_xor_sync(0xffffffffu, rsum1, 1);
    rsum1 += __shfl_xor_sync(0xffffffffu, rsum1, 2);
    if (gc == 0) {
        red[row0 * 4 + wn] = rsum0;
        red[(row0 + 8) * 4 + wn] = rsum1;
    }
    __syncthreads();
    if (tid < 32) {
        float s = red[tid * 4] + red[tid * 4 + 1] + red[tid * 4 + 2] + red[tid * 4 + 3];
        inv_s[tid] = 1.0f / s;
    }
    __syncthreads();

    // ---------- Phase B: stream probs/quasi/new from Sc (half) ----------
    // probs/quasi never re-read -> streaming stores (__stwt) keep L2 for newP.
    for (int r = w * 4; r < w * 4 + 4; r++) {
        const float inv = inv_s[r];
        const float lam = lam_s[r];
        const int qrow = qb * 32 + r;
        const float* qs_row = &g_qsig[((size_t)(bi * Ss + qrow)) * Ss];
        const size_t rowbase = ((size_t)bh * Ss + qrow) * Ss;
        float* probs_row = out + OFF_PROBS + rowbase;
        float* quasi_row = out + OFF_QUASI + rowbase;
        float* new_row   = out + OFF_NEW + rowbase;

        for (int c8 = lane; c8 < 128; c8 += 32) {
            int col = c8 * 8;
            uint4 hv = *(uint4*)&Sc[r * SC_H + col];
            const __half2* hp = (const __half2*)&hv;
            float2 e01 = __half22float2(hp[0]);
            float2 e23 = __half22float2(hp[1]);
            float2 e45 = __half22float2(hp[2]);
            float2 e67 = __half22float2(hp[3]);
            float4 p0 = {e01.x * inv, e01.y * inv, e23.x * inv, e23.y * inv};
            float4 p1 = {e45.x * inv, e45.y * inv, e67.x * inv, e67.y * inv};
            float4 qs0 = *(const float4*)&qs_row[col];
            float4 qs1 = *(const float4*)&qs_row[col + 4];
            float4 qp0 = {lam * qs0.x, lam * qs0.y, lam * qs0.z, lam * qs0.w};
            float4 qp1 = {lam * qs1.x, lam * qs1.y, lam * qs1.z, lam * qs1.w};
            float4 n0 = {p0.x + qp0.x, p0.y + qp0.y, p0.z + qp0.z, p0.w + qp0.w};
            float4 n1 = {p1.x + qp1.x, p1.y + qp1.y, p1.z + qp1.z, p1.w + qp1.w};
            __stwt((float4*)&probs_row[col], p0);
            __stwt((float4*)&probs_row[col + 4], p1);
            __stwt((float4*)&quasi_row[col], qp0);
            __stwt((float4*)&quasi_row[col + 4], qp1);
            *(float4*)&new_row[col] = n0;
            *(float4*)&new_row[col + 4] = n1;
        }
    }
}

// ---------------- kernel 4: ctx = newP @ V, reverse-bh, cp.async 2-stage ----------
#define PV_SMEM ((2 * 128 * 36 + 2 * 32 * 72) * 4)

__global__ __launch_bounds__(256) void pv_gemm(float* __restrict__ out)
{
    extern __shared__ uint32_t pvs[];
    float*    Psf = (float*)pvs;            // 2 x 128*36
    uint32_t* Vs  = pvs + 2 * 128 * 36;     // 2 x 32*72

    const int qt = blockIdx.x;
    const int bh = 63 - blockIdx.y;         // reverse: read freshest newP first
    const int bi = bh >> 4, hi = bh & 15;
    const int tid = threadIdx.x;
    const int warpId = tid >> 5, lane = tid & 31;
    const int wm = warpId & 3, wn = warpId >> 2;
    const int gr = lane >> 2, gc = lane & 3;

    const size_t OFF_NEW = (size_t)Bb * Ss * Dd;
    const float* newb = out + OFF_NEW + ((size_t)bh * Ss + qt * 128) * Ss;
    const uint32_t* Vtg = &g_Vt[(size_t)bh * Ss * 64];

    float acc[2][4][4];
#pragma unroll
    for (int m = 0; m < 2; m++)
#pragma unroll
        for (int t = 0; t < 4; t++)
#pragma unroll
            for (int e = 0; e < 4; e++) acc[m][t][e] = 0.0f;

    auto issue = [&](int st, int kt) {
#pragma unroll
        for (int i = 0; i < 4; i++) {
            int idx = tid + i * 256;
            int r = idx >> 3, c4 = idx & 7;
            cpa16(&Psf[st * 4608 + r * 36 + c4 * 4],
                  &newb[(size_t)r * 1024 + kt * 32 + c4 * 4]);
        }
#pragma unroll
        for (int i = 0; i < 2; i++) {
            int idx = tid + i * 256;
            int k = idx >> 4, c4 = idx & 15;
            cpa16(&Vs[st * 2304 + k * 72 + c4 * 4],
                  &Vtg[((size_t)(kt * 32 + k)) * 64 + c4 * 4]);
        }
        asm volatile("cp.async.commit_group;");
    };

    issue(0, 0);

    for (int kt = 0; kt < 32; kt++) {
        if (kt < 31) {
            issue((kt + 1) & 1, kt + 1);
            asm volatile("cp.async.wait_group 1;");
        } else {
            asm volatile("cp.async.wait_group 0;");
        }
        __syncthreads();

        const float* Pst = Psf + (kt & 1) * 4608;
        const uint32_t* Vst = Vs + (kt & 1) * 2304;
#pragma unroll
        for (int ks = 0; ks < 4; ks++) {
            const int kb = ks * 8;
            uint32_t af[2][4];
#pragma unroll
            for (int m = 0; m < 2; m++) {
                int m0 = wm * 32 + m * 16;
                af[m][0] = f2tf(Pst[(m0 + gr) * 36 + kb + gc]);
                af[m][1] = f2tf(Pst[(m0 + gr + 8) * 36 + kb + gc]);
                af[m][2] = f2tf(Pst[(m0 + gr) * 36 + kb + gc + 4]);
                af[m][3] = f2tf(Pst[(m0 + gr + 8) * 36 + kb + gc + 4]);
            }
#pragma unroll
            for (int t = 0; t < 4; t++) {
                int n0 = wn * 32 + t * 8;
                uint32_t bf[2];
                bf[0] = Vst[(kb + gc) * 72 + n0 + gr];
                bf[1] = Vst[(kb + gc + 4) * 72 + n0 + gr];
                mma_tf32(acc[0][t], af[0], bf);
                mma_tf32(acc[1][t], af[1], bf);
            }
        }
        __syncthreads();
    }

#pragma unroll
    for (int m = 0; m < 2; m++) {
        int row0 = qt * 128 + wm * 32 + m * 16 + gr;
#pragma unroll
        for (int t = 0; t < 4; t++) {
            int col = hi * 64 + wn * 32 + t * 8 + gc * 2;
            float2 v0 = {acc[m][t][0], acc[m][t][1]};
            float2 v1 = {acc[m][t][2], acc[m][t][3]};
            *(float2*)&out[((size_t)(bi * Ss + row0)) * Dd + col] = v0;
            *(float2*)&out[((size_t)(bi * Ss + row0 + 8)) * Dd + col] = v1;
        }
    }
}

// ---------------- launch ----------------------------------------------------------
extern "C" void kernel_launch(void* const* d_in, const int* in_sizes, int n_in,
                              void* d_out, int out_size)
{
    (void)in_sizes; (void)n_in; (void)out_size;
    const float* hidden = (const float*)d_in[0];
    const float* mask   = (const float*)d_in[1];
    const float* ctxemb = (const float*)d_in[2];
    const float* Wq = (const float*)d_in[3];  const float* bq = (const float*)d_in[4];
    const float* Wk = (const float*)d_in[5];  const float* bk = (const float*)d_in[6];
    const float* Wv = (const float*)d_in[7];  const float* bv = (const float*)d_in[8];
    const float* Wcq = (const float*)d_in[9]; const float* bcq = (const float*)d_in[10];
    const float* Wck = (const float*)d_in[11];const float* bck = (const float*)d_in[12];
    const float* wlqc = (const float*)d_in[13];
    const float* wlqq = (const float*)d_in[14];
    const float* wlkc = (const float*)d_in[15];
    const float* wlkk = (const float*)d_in[16];
    float* out = (float*)d_out;

    cudaFuncSetAttribute(proj_h, cudaFuncAttributeMaxDynamicSharedMemorySize, PROJ_SMEM);
    cudaFuncSetAttribute(attn_ab, cudaFuncAttributeMaxDynamicSharedMemorySize, ATTN_SMEM);
    cudaFuncSetAttribute(pv_gemm, cudaFuncAttributeMaxDynamicSharedMemorySize, PV_SMEM);

    // user launch index 3 = attn_ab (profiled by ncu this round)
    conv_cqck<<<1824, 256>>>(hidden, Wq, Wk, Wv, ctxemb, Wcq, bcq, Wck, bck);  // 0
    qsig_kernel<<<dim3(16, 16, Bb), 256>>>(mask);                              // 1
    proj_h<<<dim3(8, 32, 3), 256, PROJ_SMEM>>>(bq, bk, bv);                    // 2
    attn_ab<<<dim3(32, 64), 256, ATTN_SMEM>>>(mask, out, wlqc, wlqq, wlkc, wlkk); // 3
    pv_gemm<<<dim3(8, 64), 256, PV_SMEM>>>(out);                               // 4
}